// round 1
// baseline (speedup 1.0000x reference)
#include <cuda_runtime.h>
#include <cstdint>

// ---------------------------------------------------------------------------
// Problem constants
// ---------------------------------------------------------------------------
#define BB 4
#define CC 2048
#define EE 1024
#define HH 16
#define DD 64
#define MM (BB * CC)          // 8192 rows
#define FF (4 * EE)           // 4096 mlp hidden

// Scratch: normed, q, k, v, outbuf, hbuf  (each MM*EE)  +  m1 (MM*FF)
#define NBUF ((size_t)MM * EE)                 // 8388608 floats
#define SCRATCH_FLOATS (6 * NBUF + (size_t)MM * FF)
__device__ float g_scratch[SCRATCH_FLOATS];

typedef unsigned long long u64;

__device__ __forceinline__ u64 pk2(float x, float y) {
    u64 r;
    asm("mov.b64 %0, {%1, %2};" : "=l"(r) : "f"(x), "f"(y));
    return r;
}
__device__ __forceinline__ void ffma2(u64& d, u64 a, u64 b) {
    asm("fma.rn.f32x2 %0, %1, %2, %0;" : "+l"(d) : "l"(a), "l"(b));
}
__device__ __forceinline__ float2 up2(u64 v) {
    float2 f;
    asm("mov.b64 {%0, %1}, %2;" : "=f"(f.x), "=f"(f.y) : "l"(v));
    return f;
}

// ---------------------------------------------------------------------------
// LayerNorm: one block per row of 1024
// ---------------------------------------------------------------------------
__global__ __launch_bounds__(256) void ln_kernel(
    const float* __restrict__ x, const float* __restrict__ gamma,
    const float* __restrict__ beta, float* __restrict__ y)
{
    const int row = blockIdx.x;
    const int t = threadIdx.x;
    const float4 v = ((const float4*)(x + (size_t)row * EE))[t];
    float s  = v.x + v.y + v.z + v.w;
    float s2 = fmaf(v.x, v.x, fmaf(v.y, v.y, fmaf(v.z, v.z, v.w * v.w)));
    #pragma unroll
    for (int o = 16; o > 0; o >>= 1) {
        s  += __shfl_xor_sync(0xffffffffu, s, o);
        s2 += __shfl_xor_sync(0xffffffffu, s2, o);
    }
    __shared__ float rs[8], rs2[8];
    __shared__ float sstat[2];
    if ((t & 31) == 0) { rs[t >> 5] = s; rs2[t >> 5] = s2; }
    __syncthreads();
    if (t == 0) {
        float S = 0.f, S2 = 0.f;
        #pragma unroll
        for (int w = 0; w < 8; w++) { S += rs[w]; S2 += rs2[w]; }
        float mean = S * (1.0f / EE);
        float var  = S2 * (1.0f / EE) - mean * mean;
        sstat[0] = mean;
        sstat[1] = rsqrtf(var + 1e-5f);
    }
    __syncthreads();
    const float mean = sstat[0], rstd = sstat[1];
    const float4 gv = ((const float4*)gamma)[t];
    const float4 bv = ((const float4*)beta)[t];
    float4 o;
    o.x = (v.x - mean) * rstd * gv.x + bv.x;
    o.y = (v.y - mean) * rstd * gv.y + bv.y;
    o.z = (v.z - mean) * rstd * gv.z + bv.z;
    o.w = (v.w - mean) * rstd * gv.w + bv.w;
    ((float4*)(y + (size_t)row * EE))[t] = o;
}

// ---------------------------------------------------------------------------
// SGEMM 128x128x8, 256 threads, 8x8 microtile, packed f32x2 FMA.
// C[M,N] = A[M,K] @ B[K,N] + bias  (optional relu, optional residual add)
// M % 128 == 0, N % 128 == 0, K % 8 == 0 (always true here)
// ---------------------------------------------------------------------------
__global__ __launch_bounds__(256, 2) void sgemm_kernel(
    const float* __restrict__ A, const float* __restrict__ B,
    const float* __restrict__ bias, const float* __restrict__ res,
    float* __restrict__ C, int M, int N, int K, int do_relu)
{
    __shared__ float As[8][128];
    __shared__ float Bs[8][128];

    const int tid = threadIdx.x;
    const int tx = tid & 15;       // 0..15 -> N microtile
    const int ty = tid >> 4;       // 0..15 -> M microtile
    const int row0 = blockIdx.y * 128;
    const int col0 = blockIdx.x * 128;

    const int a_row = tid >> 1;            // 0..127
    const int a_col = (tid & 1) << 2;      // 0 or 4
    const int b_row = tid >> 5;            // 0..7
    const int b_col = (tid & 31) << 2;     // 0..124

    const float* Ap = A + (size_t)(row0 + a_row) * K + a_col;
    const float* Bp = B + (size_t)b_row * N + col0 + b_col;

    u64 acc[8][4];
    #pragma unroll
    for (int i = 0; i < 8; i++)
        #pragma unroll
        for (int j = 0; j < 4; j++) acc[i][j] = 0ull;

    for (int k0 = 0; k0 < K; k0 += 8) {
        const float4 av = *(const float4*)(Ap + k0);
        const float4 bv = *(const float4*)(Bp + (size_t)k0 * N);
        As[a_col + 0][a_row] = av.x;
        As[a_col + 1][a_row] = av.y;
        As[a_col + 2][a_row] = av.z;
        As[a_col + 3][a_row] = av.w;
        *(float4*)&Bs[b_row][b_col] = bv;
        __syncthreads();
        #pragma unroll
        for (int kk = 0; kk < 8; kk++) {
            const float4 a0 = *(const float4*)&As[kk][ty * 8];
            const float4 a1 = *(const float4*)&As[kk][ty * 8 + 4];
            u64 ap[8];
            ap[0] = pk2(a0.x, a0.x); ap[1] = pk2(a0.y, a0.y);
            ap[2] = pk2(a0.z, a0.z); ap[3] = pk2(a0.w, a0.w);
            ap[4] = pk2(a1.x, a1.x); ap[5] = pk2(a1.y, a1.y);
            ap[6] = pk2(a1.z, a1.z); ap[7] = pk2(a1.w, a1.w);
            u64 bp[4];
            #pragma unroll
            for (int j = 0; j < 4; j++)
                bp[j] = *(const u64*)&Bs[kk][tx * 8 + 2 * j];
            #pragma unroll
            for (int i = 0; i < 8; i++)
                #pragma unroll
                for (int j = 0; j < 4; j++)
                    ffma2(acc[i][j], ap[i], bp[j]);
        }
        __syncthreads();
    }

    // Epilogue
    #pragma unroll
    for (int i = 0; i < 8; i++) {
        const int r = row0 + ty * 8 + i;
        #pragma unroll
        for (int j = 0; j < 4; j++) {
            const int c = col0 + tx * 8 + 2 * j;
            const size_t idx = (size_t)r * N + c;
            float2 v = up2(acc[i][j]);
            float o0 = v.x + bias[c];
            float o1 = v.y + bias[c + 1];
            if (do_relu) { o0 = fmaxf(o0, 0.f); o1 = fmaxf(o1, 0.f); }
            if (res) { o0 += res[idx]; o1 += res[idx + 1]; }
            C[idx]     = o0;
            C[idx + 1] = o1;
        }
    }
}

// ---------------------------------------------------------------------------
// Flash attention, fp32, causal. BM=BN=64, D=64, 256 threads (16x16, 4x4).
// Q/K/V layout [B,C,E] with head h at cols h*64..h*64+63.
// Writes Out = inputs + attn (residual fused).
// ---------------------------------------------------------------------------
#define ATTN_PAD 65
#define ATTN_SMEM_FLOATS (4 * 64 * ATTN_PAD + 3 * 64)
#define ATTN_SMEM_BYTES  (ATTN_SMEM_FLOATS * 4)

__global__ __launch_bounds__(256) void attn_kernel(
    const float* __restrict__ Q, const float* __restrict__ Kt,
    const float* __restrict__ V, const float* __restrict__ inp,
    float* __restrict__ Out)
{
    extern __shared__ float sm[];
    float* Qs  = sm;                    // [64][65]  (row, d)
    float* Ks  = Qs + 64 * ATTN_PAD;    // [64][65]  (row, d)
    float* Vs  = Ks + 64 * ATTN_PAD;    // [64][65]  (row, d)
    float* Ps  = Vs + 64 * ATTN_PAD;    // [64][65]  scores / probs
    float* rm  = Ps + 64 * ATTN_PAD;    // [64] running max
    float* rl  = rm + 64;               // [64] running sum
    float* rsc = rl + 64;               // [64] rescale factor

    const int qt = blockIdx.x;          // 0..31
    const int h  = blockIdx.y;          // 0..15
    const int b  = blockIdx.z;          // 0..3
    const int q0 = qt * 64;
    const int tid = threadIdx.x;
    const int tx = tid & 15;
    const int ty = tid >> 4;

    const size_t base = ((size_t)b * CC) * EE + (size_t)h * DD;

    // Load Q tile
    for (int i = tid; i < 64 * 16; i += 256) {
        const int r = i >> 4, c4 = (i & 15) << 2;
        const float4 v = *(const float4*)(Q + base + (size_t)(q0 + r) * EE + c4);
        float* dst = &Qs[r * ATTN_PAD + c4];
        dst[0] = v.x; dst[1] = v.y; dst[2] = v.z; dst[3] = v.w;
    }
    if (tid < 64) { rm[tid] = -3.0e38f; rl[tid] = 0.f; }

    float Oacc[4][4];
    #pragma unroll
    for (int i = 0; i < 4; i++)
        #pragma unroll
        for (int j = 0; j < 4; j++) Oacc[i][j] = 0.f;

    __syncthreads();

    for (int t = 0; t <= qt; t++) {
        const int j0 = t * 64;
        // Load K, V tiles
        for (int i = tid; i < 64 * 16; i += 256) {
            const int r = i >> 4, c4 = (i & 15) << 2;
            const float4 kv = *(const float4*)(Kt + base + (size_t)(j0 + r) * EE + c4);
            const float4 vv = *(const float4*)(V  + base + (size_t)(j0 + r) * EE + c4);
            float* kd = &Ks[r * ATTN_PAD + c4];
            kd[0] = kv.x; kd[1] = kv.y; kd[2] = kv.z; kd[3] = kv.w;
            float* vd = &Vs[r * ATTN_PAD + c4];
            vd[0] = vv.x; vd[1] = vv.y; vd[2] = vv.z; vd[3] = vv.w;
        }
        __syncthreads();

        // S = Q @ K^T
        float Sacc[4][4];
        #pragma unroll
        for (int i = 0; i < 4; i++)
            #pragma unroll
            for (int j = 0; j < 4; j++) Sacc[i][j] = 0.f;

        #pragma unroll 16
        for (int kk = 0; kk < 64; kk++) {
            float ar[4], br[4];
            #pragma unroll
            for (int i = 0; i < 4; i++) ar[i] = Qs[(ty * 4 + i) * ATTN_PAD + kk];
            #pragma unroll
            for (int j = 0; j < 4; j++) br[j] = Ks[(tx * 4 + j) * ATTN_PAD + kk];
            #pragma unroll
            for (int i = 0; i < 4; i++)
                #pragma unroll
                for (int j = 0; j < 4; j++)
                    Sacc[i][j] = fmaf(ar[i], br[j], Sacc[i][j]);
        }

        // scale + causal mask (only diagonal tile can mask), write to Ps
        const bool diag = (t == qt);
        #pragma unroll
        for (int i = 0; i < 4; i++)
            #pragma unroll
            for (int j = 0; j < 4; j++) {
                float s = Sacc[i][j] * 0.125f;
                if (diag && (j0 + tx * 4 + j > q0 + ty * 4 + i)) s = -3.0e38f;
                Ps[(ty * 4 + i) * ATTN_PAD + tx * 4 + j] = s;
            }
        __syncthreads();

        // online softmax update: 4 threads per row, 16 cols each
        {
            const int r = tid >> 2, part = tid & 3;
            float* prow = &Ps[r * ATTN_PAD + part * 16];
            float mloc = -3.0e38f;
            #pragma unroll
            for (int c = 0; c < 16; c++) mloc = fmaxf(mloc, prow[c]);
            mloc = fmaxf(mloc, __shfl_xor_sync(0xffffffffu, mloc, 1));
            mloc = fmaxf(mloc, __shfl_xor_sync(0xffffffffu, mloc, 2));
            const float mold = rm[r];
            const float mnew = fmaxf(mold, mloc);
            const float corr = __expf(mold - mnew);
            float sloc = 0.f;
            #pragma unroll
            for (int c = 0; c < 16; c++) {
                const float p = __expf(prow[c] - mnew);
                prow[c] = p;
                sloc += p;
            }
            sloc += __shfl_xor_sync(0xffffffffu, sloc, 1);
            sloc += __shfl_xor_sync(0xffffffffu, sloc, 2);
            if (part == 0) {
                rl[r] = rl[r] * corr + sloc;
                rm[r] = mnew;
                rsc[r] = corr;
            }
        }
        __syncthreads();

        // rescale O, accumulate O += P @ V
        float cr[4];
        #pragma unroll
        for (int i = 0; i < 4; i++) cr[i] = rsc[ty * 4 + i];
        #pragma unroll
        for (int i = 0; i < 4; i++)
            #pragma unroll
            for (int j = 0; j < 4; j++) Oacc[i][j] *= cr[i];

        #pragma unroll 16
        for (int kk = 0; kk < 64; kk++) {
            float ar[4], br[4];
            #pragma unroll
            for (int i = 0; i < 4; i++) ar[i] = Ps[(ty * 4 + i) * ATTN_PAD + kk];
            #pragma unroll
            for (int j = 0; j < 4; j++) br[j] = Vs[kk * ATTN_PAD + tx * 4 + j];
            #pragma unroll
            for (int i = 0; i < 4; i++)
                #pragma unroll
                for (int j = 0; j < 4; j++)
                    Oacc[i][j] = fmaf(ar[i], br[j], Oacc[i][j]);
        }
        __syncthreads();
    }

    // finalize: divide by row sum, add residual input, store
    float linv[4];
    #pragma unroll
    for (int i = 0; i < 4; i++) linv[i] = 1.0f / rl[ty * 4 + i];
    #pragma unroll
    for (int i = 0; i < 4; i++)
        #pragma unroll
        for (int j = 0; j < 4; j++) {
            const size_t idx = base + (size_t)(q0 + ty * 4 + i) * EE + tx * 4 + j;
            Out[idx] = inp[idx] + Oacc[i][j] * linv[i];
        }
}

// ---------------------------------------------------------------------------
// kernel_launch
// ---------------------------------------------------------------------------
extern "C" void kernel_launch(void* const* d_in, const int* in_sizes, int n_in,
                              void* d_out, int out_size)
{
    const float* inputs = (const float*)d_in[0];
    const float* Wq     = (const float*)d_in[1];
    const float* bq     = (const float*)d_in[2];
    const float* Wk     = (const float*)d_in[3];
    const float* bk     = (const float*)d_in[4];
    const float* Wv     = (const float*)d_in[5];
    const float* bv     = (const float*)d_in[6];
    const float* g1     = (const float*)d_in[7];
    const float* beta1  = (const float*)d_in[8];
    const float* g2     = (const float*)d_in[9];
    const float* beta2  = (const float*)d_in[10];
    const float* W1     = (const float*)d_in[11];
    const float* bm1    = (const float*)d_in[12];
    const float* W2     = (const float*)d_in[13];
    const float* bm2    = (const float*)d_in[14];
    float* out = (float*)d_out;

    float* scratch = nullptr;
    cudaGetSymbolAddress((void**)&scratch, g_scratch);
    float* normed = scratch;
    float* qb     = normed + NBUF;
    float* kb     = qb + NBUF;
    float* vb     = kb + NBUF;
    float* outbuf = vb + NBUF;
    float* hbuf   = outbuf + NBUF;
    float* m1     = hbuf + NBUF;

    cudaFuncSetAttribute(attn_kernel,
                         cudaFuncAttributeMaxDynamicSharedMemorySize,
                         ATTN_SMEM_BYTES);

    // 1. LN1
    ln_kernel<<<MM, 256>>>(inputs, g1, beta1, normed);

    // 2. QKV projections
    dim3 gqkv(EE / 128, MM / 128);
    sgemm_kernel<<<gqkv, 256>>>(normed, Wq, bq, nullptr, qb, MM, EE, EE, 0);
    sgemm_kernel<<<gqkv, 256>>>(normed, Wk, bk, nullptr, kb, MM, EE, EE, 0);
    sgemm_kernel<<<gqkv, 256>>>(normed, Wv, bv, nullptr, vb, MM, EE, EE, 0);

    // 3. causal attention + residual (outbuf = inputs + attn)
    attn_kernel<<<dim3(CC / 64, HH, BB), 256, ATTN_SMEM_BYTES>>>(
        qb, kb, vb, inputs, outbuf);

    // 4. LN2
    ln_kernel<<<MM, 256>>>(outbuf, g2, beta2, hbuf);

    // 5. MLP
    sgemm_kernel<<<dim3(FF / 128, MM / 128), 256>>>(hbuf, W1, bm1, nullptr, m1,
                                                    MM, FF, EE, 1);
    sgemm_kernel<<<dim3(EE / 128, MM / 128), 256>>>(m1, W2, bm2, outbuf, out,
                                                    MM, EE, FF, 0);
}

// round 4
// speedup vs baseline: 1.8701x; 1.8701x over previous
#include <cuda_runtime.h>
#include <cuda_bf16.h>
#include <cstdint>

// ---------------------------------------------------------------------------
// Problem constants
// ---------------------------------------------------------------------------
#define BB 4
#define CC 2048
#define EE 1024
#define HH 16
#define DD 64
#define MM (BB * CC)          // 8192 rows
#define FF (4 * EE)           // 4096 mlp hidden

// ---------------------------------------------------------------------------
// Scratch (one big __device__ array; offsets in bytes)
// ---------------------------------------------------------------------------
#define MB (1ull << 20)
__device__ __align__(256) unsigned char g_scratch[364 * MB];

#define OFF_NH    (0 * MB)
#define OFF_NL    (16 * MB)
#define OFF_HH    (32 * MB)
#define OFF_HL    (48 * MB)
#define OFF_QB    (64 * MB)
#define OFF_KB    (96 * MB)
#define OFF_VB    (128 * MB)
#define OFF_OUTB  (160 * MB)
#define OFF_M1H   (192 * MB)
#define OFF_M1L   (256 * MB)
#define OFF_WQH   (320 * MB)
#define OFF_WQL   (322 * MB)
#define OFF_WKH   (324 * MB)
#define OFF_WKL   (326 * MB)
#define OFF_WVH   (328 * MB)
#define OFF_WVL   (330 * MB)
#define OFF_W1H   (332 * MB)
#define OFF_W1L   (340 * MB)
#define OFF_W2H   (348 * MB)
#define OFF_W2L   (356 * MB)

// ---------------------------------------------------------------------------
// PTX helpers (all baseline sm_90/compute_103 — NO 'a'-only instructions)
// ---------------------------------------------------------------------------
__device__ __forceinline__ uint32_t smem_u32(const void* p) {
    uint32_t a;
    asm("{ .reg .u64 t; cvta.to.shared.u64 t, %1; cvt.u32.u64 %0, t; }"
        : "=r"(a) : "l"(p));
    return a;
}
__device__ __forceinline__ void cpa16(uint32_t d, const void* s) {
    asm volatile("cp.async.cg.shared.global [%0], [%1], 16;" :: "r"(d), "l"(s));
}
#define CP_COMMIT() asm volatile("cp.async.commit_group;" ::: "memory")

__device__ __forceinline__ void ldsm4(uint32_t* r, uint32_t addr) {
    asm volatile("ldmatrix.sync.aligned.m8n8.x4.shared.b16 {%0,%1,%2,%3}, [%4];"
                 : "=r"(r[0]), "=r"(r[1]), "=r"(r[2]), "=r"(r[3]) : "r"(addr));
}
__device__ __forceinline__ void mma16816(float* c, const uint32_t* a,
                                         const uint32_t* b) {
    asm volatile(
        "mma.sync.aligned.m16n8k16.row.col.f32.bf16.bf16.f32 "
        "{%0,%1,%2,%3}, {%4,%5,%6,%7}, {%8,%9}, {%0,%1,%2,%3};"
        : "+f"(c[0]), "+f"(c[1]), "+f"(c[2]), "+f"(c[3])
        : "r"(a[0]), "r"(a[1]), "r"(a[2]), "r"(a[3]), "r"(b[0]), "r"(b[1]));
}

// ---------------------------------------------------------------------------
// Weight transpose + bf16 hi/lo split:  W[K,N] fp32  ->  Th/Tl [N,K] bf16
// ---------------------------------------------------------------------------
__global__ __launch_bounds__(256) void tsplit_kernel(
    const float* __restrict__ W, __nv_bfloat16* __restrict__ Th,
    __nv_bfloat16* __restrict__ Tl, int K, int N)
{
    __shared__ float t[32][33];
    const int n0 = blockIdx.x * 32, k0 = blockIdx.y * 32;
    const int tx = threadIdx.x & 31, ty = threadIdx.x >> 5;
    #pragma unroll
    for (int j = 0; j < 32; j += 8)
        t[ty + j][tx] = W[(size_t)(k0 + ty + j) * N + n0 + tx];
    __syncthreads();
    #pragma unroll
    for (int j = 0; j < 32; j += 8) {
        const float v = t[tx][ty + j];
        const __nv_bfloat16 h = __float2bfloat16(v);
        const __nv_bfloat16 l = __float2bfloat16(v - __bfloat162float(h));
        const size_t o = (size_t)(n0 + ty + j) * K + k0 + tx;
        Th[o] = h; Tl[o] = l;
    }
}

// ---------------------------------------------------------------------------
// LayerNorm: one block per row of 1024, emits bf16 hi/lo pair
// ---------------------------------------------------------------------------
__global__ __launch_bounds__(256) void ln_kernel(
    const float* __restrict__ x, const float* __restrict__ gamma,
    const float* __restrict__ beta, __nv_bfloat16* __restrict__ yh,
    __nv_bfloat16* __restrict__ yl)
{
    const int row = blockIdx.x;
    const int t = threadIdx.x;
    const float4 v = ((const float4*)(x + (size_t)row * EE))[t];
    float s  = v.x + v.y + v.z + v.w;
    float s2 = fmaf(v.x, v.x, fmaf(v.y, v.y, fmaf(v.z, v.z, v.w * v.w)));
    #pragma unroll
    for (int o = 16; o > 0; o >>= 1) {
        s  += __shfl_xor_sync(0xffffffffu, s, o);
        s2 += __shfl_xor_sync(0xffffffffu, s2, o);
    }
    __shared__ float rs[8], rs2[8];
    __shared__ float sstat[2];
    if ((t & 31) == 0) { rs[t >> 5] = s; rs2[t >> 5] = s2; }
    __syncthreads();
    if (t == 0) {
        float S = 0.f, S2 = 0.f;
        #pragma unroll
        for (int w = 0; w < 8; w++) { S += rs[w]; S2 += rs2[w]; }
        const float mean = S * (1.0f / EE);
        const float var  = S2 * (1.0f / EE) - mean * mean;
        sstat[0] = mean;
        sstat[1] = rsqrtf(var + 1e-5f);
    }
    __syncthreads();
    const float mean = sstat[0], rstd = sstat[1];
    const float4 gv = ((const float4*)gamma)[t];
    const float4 bv = ((const float4*)beta)[t];
    float o0 = (v.x - mean) * rstd * gv.x + bv.x;
    float o1 = (v.y - mean) * rstd * gv.y + bv.y;
    float o2 = (v.z - mean) * rstd * gv.z + bv.z;
    float o3 = (v.w - mean) * rstd * gv.w + bv.w;
    __nv_bfloat16 h0 = __float2bfloat16(o0), h1 = __float2bfloat16(o1);
    __nv_bfloat16 h2 = __float2bfloat16(o2), h3 = __float2bfloat16(o3);
    __nv_bfloat16 l0 = __float2bfloat16(o0 - __bfloat162float(h0));
    __nv_bfloat16 l1 = __float2bfloat16(o1 - __bfloat162float(h1));
    __nv_bfloat16 l2 = __float2bfloat16(o2 - __bfloat162float(h2));
    __nv_bfloat16 l3 = __float2bfloat16(o3 - __bfloat162float(h3));
    __nv_bfloat162* ph = (__nv_bfloat162*)(yh + (size_t)row * EE + 4 * t);
    __nv_bfloat162* pl = (__nv_bfloat162*)(yl + (size_t)row * EE + 4 * t);
    ph[0] = __halves2bfloat162(h0, h1);
    ph[1] = __halves2bfloat162(h2, h3);
    pl[0] = __halves2bfloat162(l0, l1);
    pl[1] = __halves2bfloat162(l2, l3);
}

// ---------------------------------------------------------------------------
// mma.sync bf16x3 GEMM: D[M,N] = A[M,K] @ Bt[N,K]^T  (~fp32 via hi/lo)
// Block 128x128, 8 warps (2x4), warp tile 64x32, K-chunk 32,
// 3-stage cp.async pipeline. smem rows padded to 80B (conflict-free ldmatrix).
// Epilogue: +bias [, relu]; fp32 out (+residual) or bf16 hi/lo out.
// ---------------------------------------------------------------------------
#define ROWB 80u                 // bytes per smem row (32 bf16 + pad)
#define MATB 10240u              // 128 rows * 80B
#define STGB 40960u              // Ah, Al, Bh, Bl
#define GSM_BYTES (3 * 40960)    // 122880

__global__ __launch_bounds__(256, 1) void gemm_tc(
    const __nv_bfloat16* __restrict__ Ah, const __nv_bfloat16* __restrict__ Al,
    const __nv_bfloat16* __restrict__ Bh, const __nv_bfloat16* __restrict__ Bl,
    const float* __restrict__ bias, const float* __restrict__ res,
    float* __restrict__ Cf, __nv_bfloat16* __restrict__ Ch,
    __nv_bfloat16* __restrict__ Cl, int M, int N, int K, int relu)
{
    extern __shared__ unsigned char smem[];
    const uint32_t sbase = smem_u32(smem);
    const int tid = threadIdx.x;
    const int lane = tid & 31, wid = tid >> 5;
    const int wm = wid >> 2, wn = wid & 3;          // 2 x 4 warp grid
    const int row0 = blockIdx.y * 128, col0 = blockIdx.x * 128;

    const __nv_bfloat16* gAh = Ah + (size_t)row0 * K;
    const __nv_bfloat16* gAl = Al + (size_t)row0 * K;
    const __nv_bfloat16* gBh = Bh + (size_t)col0 * K;
    const __nv_bfloat16* gBl = Bl + (size_t)col0 * K;
    const int nch = K >> 5;

    float acc[4][4][4];
    #pragma unroll
    for (int a = 0; a < 4; a++)
        #pragma unroll
        for (int b = 0; b < 4; b++)
            #pragma unroll
            for (int c = 0; c < 4; c++) acc[a][b][c] = 0.f;

    // ldmatrix per-lane smem offsets (within a matrix, before k-step add)
    const uint32_t a_base = (uint32_t)(wm * 64 + (lane & 15)) * ROWB +
                            (((lane >> 4) << 3) << 1);
    const uint32_t b_base = (uint32_t)(wn * 32 + ((lane >> 4) << 3) + (lane & 7)) * ROWB +
                            ((((lane >> 3) & 1) << 3) << 1);

    auto load_chunk = [&](int ch, int s) {
        const int k0 = ch << 5;
        const uint32_t st = sbase + s * STGB;
        #pragma unroll
        for (int i = 0; i < 8; i++) {
            const __nv_bfloat16* src = (i < 2) ? gAh : (i < 4) ? gAl
                                     : (i < 6) ? gBh : gBl;
            const int rem = ((i & 1) << 8) + tid;
            const int r = rem >> 2, g = rem & 3;
            cpa16(st + (uint32_t)(i >> 1) * MATB + (uint32_t)r * ROWB + g * 16u,
                  src + (size_t)r * K + k0 + g * 8);
        }
    };

    auto compute_chunk = [&](int s) {
        const uint32_t st = sbase + s * STGB;
        #pragma unroll
        for (int ks = 0; ks < 32; ks += 16) {
            uint32_t aH[4][4], aL[4][4], bH[2][4], bL[2][4];
            const uint32_t ao = a_base + (ks << 1);
            #pragma unroll
            for (int mi = 0; mi < 4; mi++) {
                ldsm4(aH[mi], st + ao + (uint32_t)mi * 16 * ROWB);
                ldsm4(aL[mi], st + MATB + ao + (uint32_t)mi * 16 * ROWB);
            }
            const uint32_t bo = b_base + (ks << 1);
            #pragma unroll
            for (int p = 0; p < 2; p++) {
                ldsm4(bH[p], st + 2 * MATB + bo + (uint32_t)p * 16 * ROWB);
                ldsm4(bL[p], st + 3 * MATB + bo + (uint32_t)p * 16 * ROWB);
            }
            #pragma unroll
            for (int mi = 0; mi < 4; mi++)
                #pragma unroll
                for (int p = 0; p < 2; p++)
                    #pragma unroll
                    for (int h = 0; h < 2; h++) {
                        float* c = acc[mi][p * 2 + h];
                        mma16816(c, aH[mi], &bH[p][h * 2]);
                        mma16816(c, aH[mi], &bL[p][h * 2]);
                        mma16816(c, aL[mi], &bH[p][h * 2]);
                    }
        }
    };

    load_chunk(0, 0); CP_COMMIT();
    load_chunk(1, 1); CP_COMMIT();
    load_chunk(2, 2); CP_COMMIT();

    int s = 0;
    for (int ch = 0; ch < nch; ch++) {
        asm volatile("cp.async.wait_group 2;" ::: "memory");
        __syncthreads();
        compute_chunk(s);
        __syncthreads();
        if (ch + 3 < nch) load_chunk(ch + 3, s);
        CP_COMMIT();
        s = (s == 2) ? 0 : s + 1;
    }
    asm volatile("cp.async.wait_group 0;" ::: "memory");

    // ---------------- epilogue ----------------
    const int tr = lane >> 2, tc = (lane & 3) << 1;
    #pragma unroll
    for (int mi = 0; mi < 4; mi++) {
        #pragma unroll
        for (int ni = 0; ni < 4; ni++) {
            const int col = col0 + wn * 32 + ni * 8 + tc;
            const float2 bb = *(const float2*)&bias[col];
            #pragma unroll
            for (int hr = 0; hr < 2; hr++) {
                const int row = row0 + wm * 64 + mi * 16 + tr + hr * 8;
                float v0 = acc[mi][ni][hr * 2 + 0] + bb.x;
                float v1 = acc[mi][ni][hr * 2 + 1] + bb.y;
                if (relu) { v0 = fmaxf(v0, 0.f); v1 = fmaxf(v1, 0.f); }
                const size_t goff = (size_t)row * N + col;
                if (Cf) {
                    if (res) {
                        const float2 rv = *(const float2*)&res[goff];
                        v0 += rv.x; v1 += rv.y;
                    }
                    *(float2*)&Cf[goff] = make_float2(v0, v1);
                } else {
                    const __nv_bfloat16 h0 = __float2bfloat16(v0);
                    const __nv_bfloat16 h1 = __float2bfloat16(v1);
                    const __nv_bfloat16 l0 =
                        __float2bfloat16(v0 - __bfloat162float(h0));
                    const __nv_bfloat16 l1 =
                        __float2bfloat16(v1 - __bfloat162float(h1));
                    *(__nv_bfloat162*)&Ch[goff] = __halves2bfloat162(h0, h1);
                    *(__nv_bfloat162*)&Cl[goff] = __halves2bfloat162(l0, l1);
                }
            }
        }
    }
}

// ---------------------------------------------------------------------------
// Flash attention, fp32, causal. BM=BN=64, D=64, 256 threads (16x16, 4x4).
// Writes Out = inputs + attn (residual fused).
// ---------------------------------------------------------------------------
#define ATTN_PAD 65
#define ATTN_SMEM_FLOATS (4 * 64 * ATTN_PAD + 3 * 64)
#define ATTN_SMEM_BYTES  (ATTN_SMEM_FLOATS * 4)

__global__ __launch_bounds__(256) void attn_kernel(
    const float* __restrict__ Q, const float* __restrict__ Kt,
    const float* __restrict__ V, const float* __restrict__ inp,
    float* __restrict__ Out)
{
    extern __shared__ float sm[];
    float* Qs  = sm;
    float* Ks  = Qs + 64 * ATTN_PAD;
    float* Vs  = Ks + 64 * ATTN_PAD;
    float* Ps  = Vs + 64 * ATTN_PAD;
    float* rm  = Ps + 64 * ATTN_PAD;
    float* rl  = rm + 64;
    float* rsc = rl + 64;

    const int qt = blockIdx.x;
    const int h  = blockIdx.y;
    const int b  = blockIdx.z;
    const int q0 = qt * 64;
    const int tid = threadIdx.x;
    const int tx = tid & 15;
    const int ty = tid >> 4;

    const size_t base = ((size_t)b * CC) * EE + (size_t)h * DD;

    for (int i = tid; i < 64 * 16; i += 256) {
        const int r = i >> 4, c4 = (i & 15) << 2;
        const float4 v = *(const float4*)(Q + base + (size_t)(q0 + r) * EE + c4);
        float* dst = &Qs[r * ATTN_PAD + c4];
        dst[0] = v.x; dst[1] = v.y; dst[2] = v.z; dst[3] = v.w;
    }
    if (tid < 64) { rm[tid] = -3.0e38f; rl[tid] = 0.f; }

    float Oacc[4][4];
    #pragma unroll
    for (int i = 0; i < 4; i++)
        #pragma unroll
        for (int j = 0; j < 4; j++) Oacc[i][j] = 0.f;

    __syncthreads();

    for (int t = 0; t <= qt; t++) {
        const int j0 = t * 64;
        for (int i = tid; i < 64 * 16; i += 256) {
            const int r = i >> 4, c4 = (i & 15) << 2;
            const float4 kv = *(const float4*)(Kt + base + (size_t)(j0 + r) * EE + c4);
            const float4 vv = *(const float4*)(V  + base + (size_t)(j0 + r) * EE + c4);
            float* kd = &Ks[r * ATTN_PAD + c4];
            kd[0] = kv.x; kd[1] = kv.y; kd[2] = kv.z; kd[3] = kv.w;
            float* vd = &Vs[r * ATTN_PAD + c4];
            vd[0] = vv.x; vd[1] = vv.y; vd[2] = vv.z; vd[3] = vv.w;
        }
        __syncthreads();

        float Sacc[4][4];
        #pragma unroll
        for (int i = 0; i < 4; i++)
            #pragma unroll
            for (int j = 0; j < 4; j++) Sacc[i][j] = 0.f;

        #pragma unroll 16
        for (int kk = 0; kk < 64; kk++) {
            float ar[4], br[4];
            #pragma unroll
            for (int i = 0; i < 4; i++) ar[i] = Qs[(ty * 4 + i) * ATTN_PAD + kk];
            #pragma unroll
            for (int j = 0; j < 4; j++) br[j] = Ks[(tx * 4 + j) * ATTN_PAD + kk];
            #pragma unroll
            for (int i = 0; i < 4; i++)
                #pragma unroll
                for (int j = 0; j < 4; j++)
                    Sacc[i][j] = fmaf(ar[i], br[j], Sacc[i][j]);
        }

        const bool diag = (t == qt);
        #pragma unroll
        for (int i = 0; i < 4; i++)
            #pragma unroll
            for (int j = 0; j < 4; j++) {
                float s = Sacc[i][j] * 0.125f;
                if (diag && (j0 + tx * 4 + j > q0 + ty * 4 + i)) s = -3.0e38f;
                Ps[(ty * 4 + i) * ATTN_PAD + tx * 4 + j] = s;
            }
        __syncthreads();

        {
            const int r = tid >> 2, part = tid & 3;
            float* prow = &Ps[r * ATTN_PAD + part * 16];
            float mloc = -3.0e38f;
            #pragma unroll
            for (int c = 0; c < 16; c++) mloc = fmaxf(mloc, prow[c]);
            mloc = fmaxf(mloc, __shfl_xor_sync(0xffffffffu, mloc, 1));
            mloc = fmaxf(mloc, __shfl_xor_sync(0xffffffffu, mloc, 2));
            const float mold = rm[r];
            const float mnew = fmaxf(mold, mloc);
            const float corr = __expf(mold - mnew);
            float sloc = 0.f;
            #pragma unroll
            for (int c = 0; c < 16; c++) {
                const float p = __expf(prow[c] - mnew);
                prow[c] = p;
                sloc += p;
            }
            sloc += __shfl_xor_sync(0xffffffffu, sloc, 1);
            sloc += __shfl_xor_sync(0xffffffffu, sloc, 2);
            if (part == 0) {
                rl[r] = rl[r] * corr + sloc;
                rm[r] = mnew;
                rsc[r] = corr;
            }
        }
        __syncthreads();

        float cr[4];
        #pragma unroll
        for (int i = 0; i < 4; i++) cr[i] = rsc[ty * 4 + i];
        #pragma unroll
        for (int i = 0; i < 4; i++)
            #pragma unroll
            for (int j = 0; j < 4; j++) Oacc[i][j] *= cr[i];

        #pragma unroll 16
        for (int kk = 0; kk < 64; kk++) {
            float ar[4], br[4];
            #pragma unroll
            for (int i = 0; i < 4; i++) ar[i] = Ps[(ty * 4 + i) * ATTN_PAD + kk];
            #pragma unroll
            for (int j = 0; j < 4; j++) br[j] = Vs[kk * ATTN_PAD + tx * 4 + j];
            #pragma unroll
            for (int i = 0; i < 4; i++)
                #pragma unroll
                for (int j = 0; j < 4; j++)
                    Oacc[i][j] = fmaf(ar[i], br[j], Oacc[i][j]);
        }
        __syncthreads();
    }

    float linv[4];
    #pragma unroll
    for (int i = 0; i < 4; i++) linv[i] = 1.0f / rl[ty * 4 + i];
    #pragma unroll
    for (int i = 0; i < 4; i++)
        #pragma unroll
        for (int j = 0; j < 4; j++) {
            const size_t idx = base + (size_t)(q0 + ty * 4 + i) * EE + tx * 4 + j;
            Out[idx] = inp[idx] + Oacc[i][j] * linv[i];
        }
}

// ---------------------------------------------------------------------------
// kernel_launch
// ---------------------------------------------------------------------------
extern "C" void kernel_launch(void* const* d_in, const int* in_sizes, int n_in,
                              void* d_out, int out_size)
{
    const float* inputs = (const float*)d_in[0];
    const float* Wq     = (const float*)d_in[1];
    const float* bq     = (const float*)d_in[2];
    const float* Wk     = (const float*)d_in[3];
    const float* bk     = (const float*)d_in[4];
    const float* Wv     = (const float*)d_in[5];
    const float* bv     = (const float*)d_in[6];
    const float* g1     = (const float*)d_in[7];
    const float* beta1  = (const float*)d_in[8];
    const float* g2     = (const float*)d_in[9];
    const float* beta2  = (const float*)d_in[10];
    const float* W1     = (const float*)d_in[11];
    const float* bm1    = (const float*)d_in[12];
    const float* W2     = (const float*)d_in[13];
    const float* bm2    = (const float*)d_in[14];
    float* out = (float*)d_out;

    unsigned char* base = nullptr;
    cudaGetSymbolAddress((void**)&base, g_scratch);
    __nv_bfloat16* nh   = (__nv_bfloat16*)(base + OFF_NH);
    __nv_bfloat16* nl   = (__nv_bfloat16*)(base + OFF_NL);
    __nv_bfloat16* hh   = (__nv_bfloat16*)(base + OFF_HH);
    __nv_bfloat16* hl   = (__nv_bfloat16*)(base + OFF_HL);
    float* qb           = (float*)(base + OFF_QB);
    float* kb           = (float*)(base + OFF_KB);
    float* vb           = (float*)(base + OFF_VB);
    float* outbuf       = (float*)(base + OFF_OUTB);
    __nv_bfloat16* m1h  = (__nv_bfloat16*)(base + OFF_M1H);
    __nv_bfloat16* m1l  = (__nv_bfloat16*)(base + OFF_M1L);
    __nv_bfloat16* WqTh = (__nv_bfloat16*)(base + OFF_WQH);
    __nv_bfloat16* WqTl = (__nv_bfloat16*)(base + OFF_WQL);
    __nv_bfloat16* WkTh = (__nv_bfloat16*)(base + OFF_WKH);
    __nv_bfloat16* WkTl = (__nv_bfloat16*)(base + OFF_WKL);
    __nv_bfloat16* WvTh = (__nv_bfloat16*)(base + OFF_WVH);
    __nv_bfloat16* WvTl = (__nv_bfloat16*)(base + OFF_WVL);
    __nv_bfloat16* W1Th = (__nv_bfloat16*)(base + OFF_W1H);
    __nv_bfloat16* W1Tl = (__nv_bfloat16*)(base + OFF_W1L);
    __nv_bfloat16* W2Th = (__nv_bfloat16*)(base + OFF_W2H);
    __nv_bfloat16* W2Tl = (__nv_bfloat16*)(base + OFF_W2L);

    cudaFuncSetAttribute(gemm_tc, cudaFuncAttributeMaxDynamicSharedMemorySize,
                         GSM_BYTES);
    cudaFuncSetAttribute(attn_kernel, cudaFuncAttributeMaxDynamicSharedMemorySize,
                         ATTN_SMEM_BYTES);

    // 0. weight prep: transpose + bf16 hi/lo split
    tsplit_kernel<<<dim3(EE / 32, EE / 32), 256>>>(Wq, WqTh, WqTl, EE, EE);
    tsplit_kernel<<<dim3(EE / 32, EE / 32), 256>>>(Wk, WkTh, WkTl, EE, EE);
    tsplit_kernel<<<dim3(EE / 32, EE / 32), 256>>>(Wv, WvTh, WvTl, EE, EE);
    tsplit_kernel<<<dim3(FF / 32, EE / 32), 256>>>(W1, W1Th, W1Tl, EE, FF);
    tsplit_kernel<<<dim3(EE / 32, FF / 32), 256>>>(W2, W2Th, W2Tl, FF, EE);

    // 1. LN1 -> bf16 pair
    ln_kernel<<<MM, 256>>>(inputs, g1, beta1, nh, nl);

    // 2. QKV projections (tensor cores via mma.sync)
    dim3 gqkv(EE / 128, MM / 128);
    gemm_tc<<<gqkv, 256, GSM_BYTES>>>(nh, nl, WqTh, WqTl, bq, nullptr, qb,
                                      nullptr, nullptr, MM, EE, EE, 0);
    gemm_tc<<<gqkv, 256, GSM_BYTES>>>(nh, nl, WkTh, WkTl, bk, nullptr, kb,
                                      nullptr, nullptr, MM, EE, EE, 0);
    gemm_tc<<<gqkv, 256, GSM_BYTES>>>(nh, nl, WvTh, WvTl, bv, nullptr, vb,
                                      nullptr, nullptr, MM, EE, EE, 0);

    // 3. causal attention + residual
    attn_kernel<<<dim3(CC / 64, HH, BB), 256, ATTN_SMEM_BYTES>>>(
        qb, kb, vb, inputs, outbuf);

    // 4. LN2 -> bf16 pair
    ln_kernel<<<MM, 256>>>(outbuf, g2, beta2, hh, hl);

    // 5. MLP: m1 = relu(h@W1+b) as bf16 pair; out = outbuf + m1@W2+b
    gemm_tc<<<dim3(FF / 128, MM / 128), 256, GSM_BYTES>>>(
        hh, hl, W1Th, W1Tl, bm1, nullptr, nullptr, m1h, m1l, MM, FF, EE, 1);
    gemm_tc<<<dim3(EE / 128, MM / 128), 256, GSM_BYTES>>>(
        m1h, m1l, W2Th, W2Tl, bm2, outbuf, out, nullptr, nullptr, MM, EE, FF, 0);
}

// round 5
// speedup vs baseline: 2.8431x; 1.5203x over previous
#include <cuda_runtime.h>
#include <cuda_bf16.h>
#include <cstdint>

// ---------------------------------------------------------------------------
// Problem constants
// ---------------------------------------------------------------------------
#define BB 4
#define CC 2048
#define EE 1024
#define HH 16
#define DD 64
#define MM (BB * CC)          // 8192 rows
#define FF (4 * EE)           // 4096 mlp hidden

// ---------------------------------------------------------------------------
// Scratch
// ---------------------------------------------------------------------------
#define MB (1ull << 20)
__device__ __align__(256) unsigned char g_scratch[364 * MB];

#define OFF_NH    (0 * MB)
#define OFF_NL    (16 * MB)
#define OFF_HH    (32 * MB)
#define OFF_HL    (48 * MB)
#define OFF_QH    (64 * MB)
#define OFF_QL    (80 * MB)
#define OFF_KH    (96 * MB)
#define OFF_KL    (112 * MB)
#define OFF_VH    (128 * MB)
#define OFF_VL    (144 * MB)
#define OFF_OUTB  (160 * MB)
#define OFF_M1H   (192 * MB)
#define OFF_M1L   (256 * MB)
#define OFF_WQH   (320 * MB)
#define OFF_WQL   (322 * MB)
#define OFF_WKH   (324 * MB)
#define OFF_WKL   (326 * MB)
#define OFF_WVH   (328 * MB)
#define OFF_WVL   (330 * MB)
#define OFF_W1H   (332 * MB)
#define OFF_W1L   (340 * MB)
#define OFF_W2H   (348 * MB)
#define OFF_W2L   (356 * MB)

// ---------------------------------------------------------------------------
// PTX helpers (baseline compute_103 only — no 'a' features)
// ---------------------------------------------------------------------------
__device__ __forceinline__ uint32_t smem_u32(const void* p) {
    uint32_t a;
    asm("{ .reg .u64 t; cvta.to.shared.u64 t, %1; cvt.u32.u64 %0, t; }"
        : "=r"(a) : "l"(p));
    return a;
}
__device__ __forceinline__ void cpa16(uint32_t d, const void* s) {
    asm volatile("cp.async.cg.shared.global [%0], [%1], 16;" :: "r"(d), "l"(s));
}
#define CP_COMMIT() asm volatile("cp.async.commit_group;" ::: "memory")

__device__ __forceinline__ void ldsm4(uint32_t* r, uint32_t addr) {
    asm volatile("ldmatrix.sync.aligned.m8n8.x4.shared.b16 {%0,%1,%2,%3}, [%4];"
                 : "=r"(r[0]), "=r"(r[1]), "=r"(r[2]), "=r"(r[3]) : "r"(addr));
}
__device__ __forceinline__ void ldsm4t(uint32_t* r, uint32_t addr) {
    asm volatile("ldmatrix.sync.aligned.m8n8.x4.trans.shared.b16 {%0,%1,%2,%3}, [%4];"
                 : "=r"(r[0]), "=r"(r[1]), "=r"(r[2]), "=r"(r[3]) : "r"(addr));
}
__device__ __forceinline__ void mma16816(float* c, const uint32_t* a,
                                         const uint32_t* b) {
    asm volatile(
        "mma.sync.aligned.m16n8k16.row.col.f32.bf16.bf16.f32 "
        "{%0,%1,%2,%3}, {%4,%5,%6,%7}, {%8,%9}, {%0,%1,%2,%3};"
        : "+f"(c[0]), "+f"(c[1]), "+f"(c[2]), "+f"(c[3])
        : "r"(a[0]), "r"(a[1]), "r"(a[2]), "r"(a[3]), "r"(b[0]), "r"(b[1]));
}

// pack two floats to bf16x2 (lo half = a) plus residual pack
__device__ __forceinline__ void split2(float a, float b, uint32_t& hi, uint32_t& lo) {
    const __nv_bfloat16 ha = __float2bfloat16(a), hb = __float2bfloat16(b);
    __nv_bfloat162 th = __halves2bfloat162(ha, hb);
    hi = *reinterpret_cast<uint32_t*>(&th);
    const float ra = a - __bfloat162float(ha);
    const float rb = b - __bfloat162float(hb);
    __nv_bfloat162 tl = __halves2bfloat162(__float2bfloat16(ra), __float2bfloat16(rb));
    lo = *reinterpret_cast<uint32_t*>(&tl);
}

// ---------------------------------------------------------------------------
// Weight transpose + bf16 hi/lo split:  W[K,N] fp32  ->  Th/Tl [N,K] bf16
// ---------------------------------------------------------------------------
__global__ __launch_bounds__(256) void tsplit_kernel(
    const float* __restrict__ W, __nv_bfloat16* __restrict__ Th,
    __nv_bfloat16* __restrict__ Tl, int K, int N)
{
    __shared__ float t[32][33];
    const int n0 = blockIdx.x * 32, k0 = blockIdx.y * 32;
    const int tx = threadIdx.x & 31, ty = threadIdx.x >> 5;
    #pragma unroll
    for (int j = 0; j < 32; j += 8)
        t[ty + j][tx] = W[(size_t)(k0 + ty + j) * N + n0 + tx];
    __syncthreads();
    #pragma unroll
    for (int j = 0; j < 32; j += 8) {
        const float v = t[tx][ty + j];
        const __nv_bfloat16 h = __float2bfloat16(v);
        const __nv_bfloat16 l = __float2bfloat16(v - __bfloat162float(h));
        const size_t o = (size_t)(n0 + ty + j) * K + k0 + tx;
        Th[o] = h; Tl[o] = l;
    }
}

// ---------------------------------------------------------------------------
// LayerNorm -> bf16 hi/lo
// ---------------------------------------------------------------------------
__global__ __launch_bounds__(256) void ln_kernel(
    const float* __restrict__ x, const float* __restrict__ gamma,
    const float* __restrict__ beta, __nv_bfloat16* __restrict__ yh,
    __nv_bfloat16* __restrict__ yl)
{
    const int row = blockIdx.x;
    const int t = threadIdx.x;
    const float4 v = ((const float4*)(x + (size_t)row * EE))[t];
    float s  = v.x + v.y + v.z + v.w;
    float s2 = fmaf(v.x, v.x, fmaf(v.y, v.y, fmaf(v.z, v.z, v.w * v.w)));
    #pragma unroll
    for (int o = 16; o > 0; o >>= 1) {
        s  += __shfl_xor_sync(0xffffffffu, s, o);
        s2 += __shfl_xor_sync(0xffffffffu, s2, o);
    }
    __shared__ float rs[8], rs2[8];
    __shared__ float sstat[2];
    if ((t & 31) == 0) { rs[t >> 5] = s; rs2[t >> 5] = s2; }
    __syncthreads();
    if (t == 0) {
        float S = 0.f, S2 = 0.f;
        #pragma unroll
        for (int w = 0; w < 8; w++) { S += rs[w]; S2 += rs2[w]; }
        const float mean = S * (1.0f / EE);
        const float var  = S2 * (1.0f / EE) - mean * mean;
        sstat[0] = mean;
        sstat[1] = rsqrtf(var + 1e-5f);
    }
    __syncthreads();
    const float mean = sstat[0], rstd = sstat[1];
    const float4 gv = ((const float4*)gamma)[t];
    const float4 bv = ((const float4*)beta)[t];
    float o0 = (v.x - mean) * rstd * gv.x + bv.x;
    float o1 = (v.y - mean) * rstd * gv.y + bv.y;
    float o2 = (v.z - mean) * rstd * gv.z + bv.z;
    float o3 = (v.w - mean) * rstd * gv.w + bv.w;
    uint32_t h0, l0, h1, l1;
    split2(o0, o1, h0, l0);
    split2(o2, o3, h1, l1);
    uint32_t* ph = (uint32_t*)(yh + (size_t)row * EE + 4 * t);
    uint32_t* pl = (uint32_t*)(yl + (size_t)row * EE + 4 * t);
    ph[0] = h0; ph[1] = h1;
    pl[0] = l0; pl[1] = l1;
}

// ---------------------------------------------------------------------------
// mma.sync bf16x3 GEMM, 128x128 tile, 2-stage cp.async, 2 CTAs/SM.
// ---------------------------------------------------------------------------
#define ROWB 80u
#define MATB 10240u
#define STGB 40960u
#define GSM_BYTES (2 * 40960)    // 81920

__global__ __launch_bounds__(256, 2) void gemm_tc(
    const __nv_bfloat16* __restrict__ Ah, const __nv_bfloat16* __restrict__ Al,
    const __nv_bfloat16* __restrict__ Bh, const __nv_bfloat16* __restrict__ Bl,
    const float* __restrict__ bias, const float* __restrict__ res,
    float* __restrict__ Cf, __nv_bfloat16* __restrict__ Ch,
    __nv_bfloat16* __restrict__ Cl, int M, int N, int K, int relu, float oscale)
{
    extern __shared__ unsigned char smem[];
    const uint32_t sbase = smem_u32(smem);
    const int tid = threadIdx.x;
    const int lane = tid & 31, wid = tid >> 5;
    const int wm = wid >> 2, wn = wid & 3;
    const int row0 = blockIdx.y * 128, col0 = blockIdx.x * 128;

    const __nv_bfloat16* gAh = Ah + (size_t)row0 * K;
    const __nv_bfloat16* gAl = Al + (size_t)row0 * K;
    const __nv_bfloat16* gBh = Bh + (size_t)col0 * K;
    const __nv_bfloat16* gBl = Bl + (size_t)col0 * K;
    const int nch = K >> 5;

    float acc[4][4][4];
    #pragma unroll
    for (int a = 0; a < 4; a++)
        #pragma unroll
        for (int b = 0; b < 4; b++)
            #pragma unroll
            for (int c = 0; c < 4; c++) acc[a][b][c] = 0.f;

    const uint32_t a_base = (uint32_t)(wm * 64 + (lane & 15)) * ROWB +
                            (((lane >> 4) << 3) << 1);
    const uint32_t b_base = (uint32_t)(wn * 32 + ((lane >> 4) << 3) + (lane & 7)) * ROWB +
                            ((((lane >> 3) & 1) << 3) << 1);

    auto load_chunk = [&](int ch, int s) {
        const int k0 = ch << 5;
        const uint32_t st = sbase + s * STGB;
        #pragma unroll
        for (int i = 0; i < 8; i++) {
            const __nv_bfloat16* src = (i < 2) ? gAh : (i < 4) ? gAl
                                     : (i < 6) ? gBh : gBl;
            const int rem = ((i & 1) << 8) + tid;
            const int r = rem >> 2, g = rem & 3;
            cpa16(st + (uint32_t)(i >> 1) * MATB + (uint32_t)r * ROWB + g * 16u,
                  src + (size_t)r * K + k0 + g * 8);
        }
    };

    auto compute_chunk = [&](int s) {
        const uint32_t st = sbase + s * STGB;
        #pragma unroll
        for (int ks = 0; ks < 32; ks += 16) {
            uint32_t aH[4][4], aL[4][4], bH[2][4], bL[2][4];
            const uint32_t ao = a_base + (ks << 1);
            #pragma unroll
            for (int mi = 0; mi < 4; mi++) {
                ldsm4(aH[mi], st + ao + (uint32_t)mi * 16 * ROWB);
                ldsm4(aL[mi], st + MATB + ao + (uint32_t)mi * 16 * ROWB);
            }
            const uint32_t bo = b_base + (ks << 1);
            #pragma unroll
            for (int p = 0; p < 2; p++) {
                ldsm4(bH[p], st + 2 * MATB + bo + (uint32_t)p * 16 * ROWB);
                ldsm4(bL[p], st + 3 * MATB + bo + (uint32_t)p * 16 * ROWB);
            }
            #pragma unroll
            for (int mi = 0; mi < 4; mi++)
                #pragma unroll
                for (int p = 0; p < 2; p++)
                    #pragma unroll
                    for (int h = 0; h < 2; h++) {
                        float* c = acc[mi][p * 2 + h];
                        mma16816(c, aH[mi], &bH[p][h * 2]);
                        mma16816(c, aH[mi], &bL[p][h * 2]);
                        mma16816(c, aL[mi], &bH[p][h * 2]);
                    }
        }
    };

    load_chunk(0, 0); CP_COMMIT();
    load_chunk(1, 1); CP_COMMIT();

    for (int ch = 0; ch < nch; ch++) {
        asm volatile("cp.async.wait_group 1;" ::: "memory");
        __syncthreads();
        compute_chunk(ch & 1);
        __syncthreads();
        if (ch + 2 < nch) load_chunk(ch + 2, ch & 1);
        CP_COMMIT();
    }
    asm volatile("cp.async.wait_group 0;" ::: "memory");

    // ---------------- epilogue ----------------
    const int tr = lane >> 2, tc = (lane & 3) << 1;
    #pragma unroll
    for (int mi = 0; mi < 4; mi++) {
        #pragma unroll
        for (int ni = 0; ni < 4; ni++) {
            const int col = col0 + wn * 32 + ni * 8 + tc;
            const float2 bb = *(const float2*)&bias[col];
            #pragma unroll
            for (int hr = 0; hr < 2; hr++) {
                const int row = row0 + wm * 64 + mi * 16 + tr + hr * 8;
                float v0 = acc[mi][ni][hr * 2 + 0] + bb.x;
                float v1 = acc[mi][ni][hr * 2 + 1] + bb.y;
                if (relu) { v0 = fmaxf(v0, 0.f); v1 = fmaxf(v1, 0.f); }
                v0 *= oscale; v1 *= oscale;
                const size_t goff = (size_t)row * N + col;
                if (Cf) {
                    if (res) {
                        const float2 rv = *(const float2*)&res[goff];
                        v0 += rv.x; v1 += rv.y;
                    }
                    *(float2*)&Cf[goff] = make_float2(v0, v1);
                } else {
                    uint32_t hp, lp;
                    split2(v0, v1, hp, lp);
                    *(uint32_t*)&Ch[goff] = hp;
                    *(uint32_t*)&Cl[goff] = lp;
                }
            }
        }
    }
}

// ---------------------------------------------------------------------------
// Tensor-core flash attention (causal), bf16x3 precision.
// BM=BN=64, 128 threads (4 warps, warp tile 16x64). Q pre-scaled by 1/8.
// Inputs Q/K/V as bf16 hi/lo [M][EE] with head h at cols h*64.
// Out = inp + softmax(QK^T)V  (fp32).
// ---------------------------------------------------------------------------
#define AR 144u                  // bytes per smem row (64 bf16 + 8 pad)
#define AMAT 9216u               // 64 rows * 144B
#define ASTG (4 * AMAT)          // Kh,Kl,Vh,Vl per stage
#define ATTN_SMEM (2 * AMAT + 2 * ASTG)   // Q(h,l) + 2 stages = 92160

__global__ __launch_bounds__(128) void attn_mma(
    const __nv_bfloat16* __restrict__ Qh, const __nv_bfloat16* __restrict__ Ql,
    const __nv_bfloat16* __restrict__ Kh, const __nv_bfloat16* __restrict__ Kl,
    const __nv_bfloat16* __restrict__ Vh, const __nv_bfloat16* __restrict__ Vl,
    const float* __restrict__ inp, float* __restrict__ Out)
{
    extern __shared__ unsigned char smem[];
    const uint32_t sbase = smem_u32(smem);
    const int tid = threadIdx.x, lane = tid & 31, w = tid >> 5;
    const int qt = blockIdx.x, h = blockIdx.y, b = blockIdx.z;
    const int q0 = qt * 64;
    const size_t bh = (size_t)(b * CC) * EE + (size_t)h * 64;

    // load Q tile (hi+lo)  -> group 0
    {
        const size_t ro = bh + (size_t)q0 * EE;
        #pragma unroll
        for (int i = 0; i < 4; i++) {
            const int idx = i * 128 + tid;
            const int r = idx >> 3, g = idx & 7;
            const uint32_t d = sbase + (uint32_t)r * AR + g * 16u;
            const size_t so = ro + (size_t)r * EE + g * 8;
            cpa16(d, Qh + so);
            cpa16(d + AMAT, Ql + so);
        }
    }
    CP_COMMIT();

    auto load_kv = [&](int t, int s) {
        const uint32_t st = sbase + 2 * AMAT + (uint32_t)s * ASTG;
        const size_t ro = bh + (size_t)(t * 64) * EE;
        #pragma unroll
        for (int i = 0; i < 4; i++) {
            const int idx = i * 128 + tid;
            const int r = idx >> 3, g = idx & 7;
            const uint32_t d = st + (uint32_t)r * AR + g * 16u;
            const size_t so = ro + (size_t)r * EE + g * 8;
            cpa16(d, Kh + so);
            cpa16(d + AMAT, Kl + so);
            cpa16(d + 2 * AMAT, Vh + so);
            cpa16(d + 3 * AMAT, Vl + so);
        }
    };
    load_kv(0, 0); CP_COMMIT();

    float O[8][4];
    #pragma unroll
    for (int n = 0; n < 8; n++)
        #pragma unroll
        for (int j = 0; j < 4; j++) O[n][j] = 0.f;
    float m_lo = -1e30f, m_hi = -1e30f, l_lo = 0.f, l_hi = 0.f;
    uint32_t qHf[4][4], qLf[4][4];

    const int rowl = w * 16 + (lane >> 2);       // local q row (lo); hi = +8
    const int c0 = (lane & 3) << 1;

    for (int t = 0; t <= qt; t++) {
        if (t < qt) load_kv(t + 1, (t + 1) & 1);
        CP_COMMIT();
        asm volatile("cp.async.wait_group 1;" ::: "memory");
        __syncthreads();

        const uint32_t sK = sbase + 2 * AMAT + (uint32_t)(t & 1) * ASTG;
        const uint32_t sV = sK + 2 * AMAT;

        if (t == 0) {
            const uint32_t qa = sbase + (uint32_t)(w * 16 + (lane & 15)) * AR +
                                (((lane >> 4) << 3) << 1);
            #pragma unroll
            for (int ks = 0; ks < 4; ks++) {
                ldsm4(qHf[ks], qa + ks * 32);
                ldsm4(qLf[ks], qa + AMAT + ks * 32);
            }
        }

        // ---- S = Q @ K^T (3-pass) ----
        float S[8][4];
        #pragma unroll
        for (int n = 0; n < 8; n++)
            #pragma unroll
            for (int j = 0; j < 4; j++) S[n][j] = 0.f;

        #pragma unroll
        for (int ks = 0; ks < 4; ks++) {
            #pragma unroll
            for (int np = 0; np < 4; np++) {
                const uint32_t kb = sK +
                    (uint32_t)(np * 16 + ((lane >> 4) << 3) + (lane & 7)) * AR +
                    ((((lane >> 3) & 1) << 3) << 1) + ks * 32;
                uint32_t bh4[4], bl4[4];
                ldsm4(bh4, kb);
                ldsm4(bl4, kb + AMAT);
                #pragma unroll
                for (int h2 = 0; h2 < 2; h2++) {
                    float* c = S[np * 2 + h2];
                    mma16816(c, qHf[ks], &bh4[h2 * 2]);
                    mma16816(c, qHf[ks], &bl4[h2 * 2]);
                    mma16816(c, qLf[ks], &bh4[h2 * 2]);
                }
            }
        }

        // ---- causal mask (diagonal tile only) ----
        if (t == qt) {
            #pragma unroll
            for (int n = 0; n < 8; n++) {
                const int col = n * 8 + c0;
                if (col > rowl)          S[n][0] = -1e30f;
                if (col + 1 > rowl)      S[n][1] = -1e30f;
                if (col > rowl + 8)      S[n][2] = -1e30f;
                if (col + 1 > rowl + 8)  S[n][3] = -1e30f;
            }
        }

        // ---- online softmax ----
        float mx0 = -1e30f, mx1 = -1e30f;
        #pragma unroll
        for (int n = 0; n < 8; n++) {
            mx0 = fmaxf(mx0, fmaxf(S[n][0], S[n][1]));
            mx1 = fmaxf(mx1, fmaxf(S[n][2], S[n][3]));
        }
        mx0 = fmaxf(mx0, __shfl_xor_sync(0xffffffffu, mx0, 1));
        mx0 = fmaxf(mx0, __shfl_xor_sync(0xffffffffu, mx0, 2));
        mx1 = fmaxf(mx1, __shfl_xor_sync(0xffffffffu, mx1, 1));
        mx1 = fmaxf(mx1, __shfl_xor_sync(0xffffffffu, mx1, 2));
        const float mn0 = fmaxf(m_lo, mx0), mn1 = fmaxf(m_hi, mx1);
        const float cr0 = __expf(m_lo - mn0), cr1 = __expf(m_hi - mn1);
        float s0 = 0.f, s1 = 0.f;
        #pragma unroll
        for (int n = 0; n < 8; n++) {
            S[n][0] = __expf(S[n][0] - mn0); s0 += S[n][0];
            S[n][1] = __expf(S[n][1] - mn0); s0 += S[n][1];
            S[n][2] = __expf(S[n][2] - mn1); s1 += S[n][2];
            S[n][3] = __expf(S[n][3] - mn1); s1 += S[n][3];
        }
        s0 += __shfl_xor_sync(0xffffffffu, s0, 1);
        s0 += __shfl_xor_sync(0xffffffffu, s0, 2);
        s1 += __shfl_xor_sync(0xffffffffu, s1, 1);
        s1 += __shfl_xor_sync(0xffffffffu, s1, 2);
        l_lo = l_lo * cr0 + s0; l_hi = l_hi * cr1 + s1;
        m_lo = mn0; m_hi = mn1;
        #pragma unroll
        for (int n = 0; n < 8; n++) {
            O[n][0] *= cr0; O[n][1] *= cr0;
            O[n][2] *= cr1; O[n][3] *= cr1;
        }

        // ---- P -> bf16 hi/lo A-fragments (C-frag reuse) ----
        uint32_t pH[4][4], pL[4][4];
        #pragma unroll
        for (int kk = 0; kk < 4; kk++) {
            split2(S[2 * kk][0],     S[2 * kk][1],     pH[kk][0], pL[kk][0]);
            split2(S[2 * kk][2],     S[2 * kk][3],     pH[kk][1], pL[kk][1]);
            split2(S[2 * kk + 1][0], S[2 * kk + 1][1], pH[kk][2], pL[kk][2]);
            split2(S[2 * kk + 1][2], S[2 * kk + 1][3], pH[kk][3], pL[kk][3]);
        }

        // ---- O += P @ V (3-pass, ldmatrix.trans for V) ----
        #pragma unroll
        for (int kk = 0; kk < 4; kk++) {
            #pragma unroll
            for (int np = 0; np < 4; np++) {
                const uint32_t va = sV +
                    (uint32_t)(kk * 16 + ((lane >> 3) & 1) * 8 + (lane & 7)) * AR +
                    ((np * 16 + ((lane >> 4) << 3)) << 1);
                uint32_t vh4[4], vl4[4];
                ldsm4t(vh4, va);
                ldsm4t(vl4, va + AMAT);
                #pragma unroll
                for (int h2 = 0; h2 < 2; h2++) {
                    float* c = O[np * 2 + h2];
                    mma16816(c, pH[kk], &vh4[h2 * 2]);
                    mma16816(c, pH[kk], &vl4[h2 * 2]);
                    mma16816(c, pL[kk], &vh4[h2 * 2]);
                }
            }
        }
        __syncthreads();
    }

    // ---- finalize: /l, add residual, store fp32 ----
    const float inv0 = 1.0f / l_lo, inv1 = 1.0f / l_hi;
    const int gr0 = b * CC + q0 + rowl;
    #pragma unroll
    for (int n = 0; n < 8; n++) {
        const int col = h * 64 + n * 8 + c0;
        const size_t o0 = (size_t)gr0 * EE + col;
        const size_t o1 = o0 + (size_t)8 * EE;
        const float2 i0 = *(const float2*)&inp[o0];
        const float2 i1 = *(const float2*)&inp[o1];
        *(float2*)&Out[o0] = make_float2(i0.x + O[n][0] * inv0,
                                         i0.y + O[n][1] * inv0);
        *(float2*)&Out[o1] = make_float2(i1.x + O[n][2] * inv1,
                                         i1.y + O[n][3] * inv1);
    }
}

// ---------------------------------------------------------------------------
// kernel_launch
// ---------------------------------------------------------------------------
extern "C" void kernel_launch(void* const* d_in, const int* in_sizes, int n_in,
                              void* d_out, int out_size)
{
    const float* inputs = (const float*)d_in[0];
    const float* Wq     = (const float*)d_in[1];
    const float* bq     = (const float*)d_in[2];
    const float* Wk     = (const float*)d_in[3];
    const float* bk     = (const float*)d_in[4];
    const float* Wv     = (const float*)d_in[5];
    const float* bv     = (const float*)d_in[6];
    const float* g1     = (const float*)d_in[7];
    const float* beta1  = (const float*)d_in[8];
    const float* g2     = (const float*)d_in[9];
    const float* beta2  = (const float*)d_in[10];
    const float* W1     = (const float*)d_in[11];
    const float* bm1    = (const float*)d_in[12];
    const float* W2     = (const float*)d_in[13];
    const float* bm2    = (const float*)d_in[14];
    float* out = (float*)d_out;

    unsigned char* base = nullptr;
    cudaGetSymbolAddress((void**)&base, g_scratch);
    __nv_bfloat16* nh   = (__nv_bfloat16*)(base + OFF_NH);
    __nv_bfloat16* nl   = (__nv_bfloat16*)(base + OFF_NL);
    __nv_bfloat16* hh   = (__nv_bfloat16*)(base + OFF_HH);
    __nv_bfloat16* hl   = (__nv_bfloat16*)(base + OFF_HL);
    __nv_bfloat16* qh   = (__nv_bfloat16*)(base + OFF_QH);
    __nv_bfloat16* ql   = (__nv_bfloat16*)(base + OFF_QL);
    __nv_bfloat16* kh   = (__nv_bfloat16*)(base + OFF_KH);
    __nv_bfloat16* kl   = (__nv_bfloat16*)(base + OFF_KL);
    __nv_bfloat16* vh   = (__nv_bfloat16*)(base + OFF_VH);
    __nv_bfloat16* vl   = (__nv_bfloat16*)(base + OFF_VL);
    float* outbuf       = (float*)(base + OFF_OUTB);
    __nv_bfloat16* m1h  = (__nv_bfloat16*)(base + OFF_M1H);
    __nv_bfloat16* m1l  = (__nv_bfloat16*)(base + OFF_M1L);
    __nv_bfloat16* WqTh = (__nv_bfloat16*)(base + OFF_WQH);
    __nv_bfloat16* WqTl = (__nv_bfloat16*)(base + OFF_WQL);
    __nv_bfloat16* WkTh = (__nv_bfloat16*)(base + OFF_WKH);
    __nv_bfloat16* WkTl = (__nv_bfloat16*)(base + OFF_WKL);
    __nv_bfloat16* WvTh = (__nv_bfloat16*)(base + OFF_WVH);
    __nv_bfloat16* WvTl = (__nv_bfloat16*)(base + OFF_WVL);
    __nv_bfloat16* W1Th = (__nv_bfloat16*)(base + OFF_W1H);
    __nv_bfloat16* W1Tl = (__nv_bfloat16*)(base + OFF_W1L);
    __nv_bfloat16* W2Th = (__nv_bfloat16*)(base + OFF_W2H);
    __nv_bfloat16* W2Tl = (__nv_bfloat16*)(base + OFF_W2L);

    cudaFuncSetAttribute(gemm_tc, cudaFuncAttributeMaxDynamicSharedMemorySize,
                         GSM_BYTES);
    cudaFuncSetAttribute(attn_mma, cudaFuncAttributeMaxDynamicSharedMemorySize,
                         ATTN_SMEM);

    // 0. weight prep
    tsplit_kernel<<<dim3(EE / 32, EE / 32), 256>>>(Wq, WqTh, WqTl, EE, EE);
    tsplit_kernel<<<dim3(EE / 32, EE / 32), 256>>>(Wk, WkTh, WkTl, EE, EE);
    tsplit_kernel<<<dim3(EE / 32, EE / 32), 256>>>(Wv, WvTh, WvTl, EE, EE);
    tsplit_kernel<<<dim3(FF / 32, EE / 32), 256>>>(W1, W1Th, W1Tl, EE, FF);
    tsplit_kernel<<<dim3(EE / 32, FF / 32), 256>>>(W2, W2Th, W2Tl, FF, EE);

    // 1. LN1 -> bf16 pair
    ln_kernel<<<MM, 256>>>(inputs, g1, beta1, nh, nl);

    // 2. QKV projections -> bf16 hi/lo outputs (q pre-scaled by 1/8)
    dim3 gqkv(EE / 128, MM / 128);
    gemm_tc<<<gqkv, 256, GSM_BYTES>>>(nh, nl, WqTh, WqTl, bq, nullptr, nullptr,
                                      qh, ql, MM, EE, EE, 0, 0.125f);
    gemm_tc<<<gqkv, 256, GSM_BYTES>>>(nh, nl, WkTh, WkTl, bk, nullptr, nullptr,
                                      kh, kl, MM, EE, EE, 0, 1.0f);
    gemm_tc<<<gqkv, 256, GSM_BYTES>>>(nh, nl, WvTh, WvTl, bv, nullptr, nullptr,
                                      vh, vl, MM, EE, EE, 0, 1.0f);

    // 3. tensor-core causal attention + residual
    attn_mma<<<dim3(CC / 64, HH, BB), 128, ATTN_SMEM>>>(
        qh, ql, kh, kl, vh, vl, inputs, outbuf);

    // 4. LN2 -> bf16 pair
    ln_kernel<<<MM, 256>>>(outbuf, g2, beta2, hh, hl);

    // 5. MLP
    gemm_tc<<<dim3(FF / 128, MM / 128), 256, GSM_BYTES>>>(
        hh, hl, W1Th, W1Tl, bm1, nullptr, nullptr, m1h, m1l, MM, FF, EE, 1, 1.0f);
    gemm_tc<<<dim3(EE / 128, MM / 128), 256, GSM_BYTES>>>(
        m1h, m1l, W2Th, W2Tl, bm2, outbuf, out, nullptr, nullptr, MM, EE, FF, 0, 1.0f);
}

// round 6
// speedup vs baseline: 2.8586x; 1.0055x over previous
#include <cuda_runtime.h>
#include <cuda_bf16.h>
#include <cstdint>

// ---------------------------------------------------------------------------
// Problem constants
// ---------------------------------------------------------------------------
#define BB 4
#define CC 2048
#define EE 1024
#define HH 16
#define DD 64
#define MM (BB * CC)          // 8192 rows
#define FF (4 * EE)           // 4096 mlp hidden
#define KVS 2048              // fused K|V row stride

// ---------------------------------------------------------------------------
// Scratch
// ---------------------------------------------------------------------------
#define MB (1ull << 20)
__device__ __align__(256) unsigned char g_scratch[364 * MB];

#define OFF_NH    (0 * MB)
#define OFF_NL    (16 * MB)
#define OFF_HH    (32 * MB)
#define OFF_HL    (48 * MB)
#define OFF_QH    (64 * MB)
#define OFF_QL    (80 * MB)
#define OFF_KVH   (96 * MB)     // [MM, 2048] bf16  (K cols 0-1023, V 1024-2047)
#define OFF_KVL   (128 * MB)
#define OFF_OUTB  (160 * MB)
#define OFF_M1H   (192 * MB)
#define OFF_M1L   (256 * MB)
#define OFF_WQH   (320 * MB)
#define OFF_WQL   (322 * MB)
#define OFF_WKVH  (324 * MB)    // [2048, 1024] bf16
#define OFF_WKVL  (328 * MB)
#define OFF_W1H   (332 * MB)
#define OFF_W1L   (340 * MB)
#define OFF_W2H   (348 * MB)
#define OFF_W2L   (356 * MB)

// ---------------------------------------------------------------------------
// PTX helpers (baseline compute_103 only — no 'a' features)
// ---------------------------------------------------------------------------
__device__ __forceinline__ uint32_t smem_u32(const void* p) {
    uint32_t a;
    asm("{ .reg .u64 t; cvta.to.shared.u64 t, %1; cvt.u32.u64 %0, t; }"
        : "=r"(a) : "l"(p));
    return a;
}
__device__ __forceinline__ void cpa16(uint32_t d, const void* s) {
    asm volatile("cp.async.cg.shared.global [%0], [%1], 16;" :: "r"(d), "l"(s));
}
#define CP_COMMIT() asm volatile("cp.async.commit_group;" ::: "memory")

__device__ __forceinline__ void ldsm4(uint32_t* r, uint32_t addr) {
    asm volatile("ldmatrix.sync.aligned.m8n8.x4.shared.b16 {%0,%1,%2,%3}, [%4];"
                 : "=r"(r[0]), "=r"(r[1]), "=r"(r[2]), "=r"(r[3]) : "r"(addr));
}
__device__ __forceinline__ void ldsm4t(uint32_t* r, uint32_t addr) {
    asm volatile("ldmatrix.sync.aligned.m8n8.x4.trans.shared.b16 {%0,%1,%2,%3}, [%4];"
                 : "=r"(r[0]), "=r"(r[1]), "=r"(r[2]), "=r"(r[3]) : "r"(addr));
}
__device__ __forceinline__ void mma16816(float* c, const uint32_t* a,
                                         const uint32_t* b) {
    asm volatile(
        "mma.sync.aligned.m16n8k16.row.col.f32.bf16.bf16.f32 "
        "{%0,%1,%2,%3}, {%4,%5,%6,%7}, {%8,%9}, {%0,%1,%2,%3};"
        : "+f"(c[0]), "+f"(c[1]), "+f"(c[2]), "+f"(c[3])
        : "r"(a[0]), "r"(a[1]), "r"(a[2]), "r"(a[3]), "r"(b[0]), "r"(b[1]));
}

__device__ __forceinline__ void split2(float a, float b, uint32_t& hi, uint32_t& lo) {
    const __nv_bfloat16 ha = __float2bfloat16(a), hb = __float2bfloat16(b);
    __nv_bfloat162 th = __halves2bfloat162(ha, hb);
    hi = *reinterpret_cast<uint32_t*>(&th);
    const float ra = a - __bfloat162float(ha);
    const float rb = b - __bfloat162float(hb);
    __nv_bfloat162 tl = __halves2bfloat162(__float2bfloat16(ra), __float2bfloat16(rb));
    lo = *reinterpret_cast<uint32_t*>(&tl);
}

// ---------------------------------------------------------------------------
// Weight transpose + bf16 hi/lo split:  W[K,N] fp32  ->  Th/Tl [N,K] bf16
// ---------------------------------------------------------------------------
__global__ __launch_bounds__(256) void tsplit_kernel(
    const float* __restrict__ W, __nv_bfloat16* __restrict__ Th,
    __nv_bfloat16* __restrict__ Tl, int K, int N)
{
    __shared__ float t[32][33];
    const int n0 = blockIdx.x * 32, k0 = blockIdx.y * 32;
    const int tx = threadIdx.x & 31, ty = threadIdx.x >> 5;
    #pragma unroll
    for (int j = 0; j < 32; j += 8)
        t[ty + j][tx] = W[(size_t)(k0 + ty + j) * N + n0 + tx];
    __syncthreads();
    #pragma unroll
    for (int j = 0; j < 32; j += 8) {
        const float v = t[tx][ty + j];
        const __nv_bfloat16 h = __float2bfloat16(v);
        const __nv_bfloat16 l = __float2bfloat16(v - __bfloat162float(h));
        const size_t o = (size_t)(n0 + ty + j) * K + k0 + tx;
        Th[o] = h; Tl[o] = l;
    }
}

// ---------------------------------------------------------------------------
// LayerNorm -> bf16 hi/lo
// ---------------------------------------------------------------------------
__global__ __launch_bounds__(256) void ln_kernel(
    const float* __restrict__ x, const float* __restrict__ gamma,
    const float* __restrict__ beta, __nv_bfloat16* __restrict__ yh,
    __nv_bfloat16* __restrict__ yl)
{
    const int row = blockIdx.x;
    const int t = threadIdx.x;
    const float4 v = ((const float4*)(x + (size_t)row * EE))[t];
    float s  = v.x + v.y + v.z + v.w;
    float s2 = fmaf(v.x, v.x, fmaf(v.y, v.y, fmaf(v.z, v.z, v.w * v.w)));
    #pragma unroll
    for (int o = 16; o > 0; o >>= 1) {
        s  += __shfl_xor_sync(0xffffffffu, s, o);
        s2 += __shfl_xor_sync(0xffffffffu, s2, o);
    }
    __shared__ float rs[8], rs2[8];
    __shared__ float sstat[2];
    if ((t & 31) == 0) { rs[t >> 5] = s; rs2[t >> 5] = s2; }
    __syncthreads();
    if (t == 0) {
        float S = 0.f, S2 = 0.f;
        #pragma unroll
        for (int w = 0; w < 8; w++) { S += rs[w]; S2 += rs2[w]; }
        const float mean = S * (1.0f / EE);
        const float var  = S2 * (1.0f / EE) - mean * mean;
        sstat[0] = mean;
        sstat[1] = rsqrtf(var + 1e-5f);
    }
    __syncthreads();
    const float mean = sstat[0], rstd = sstat[1];
    const float4 gv = ((const float4*)gamma)[t];
    const float4 bv = ((const float4*)beta)[t];
    float o0 = (v.x - mean) * rstd * gv.x + bv.x;
    float o1 = (v.y - mean) * rstd * gv.y + bv.y;
    float o2 = (v.z - mean) * rstd * gv.z + bv.z;
    float o3 = (v.w - mean) * rstd * gv.w + bv.w;
    uint32_t h0, l0, h1, l1;
    split2(o0, o1, h0, l0);
    split2(o2, o3, h1, l1);
    uint32_t* ph = (uint32_t*)(yh + (size_t)row * EE + 4 * t);
    uint32_t* pl = (uint32_t*)(yl + (size_t)row * EE + 4 * t);
    ph[0] = h0; ph[1] = h1;
    pl[0] = l0; pl[1] = l1;
}

// ---------------------------------------------------------------------------
// mma.sync bf16x3 GEMM, 128x128 tile, 2-stage cp.async, 2 CTAs/SM.
// bias2/nsplit: cols >= nsplit use bias2[col-nsplit] (fused KV projection).
// ---------------------------------------------------------------------------
#define ROWB 80u
#define MATB 10240u
#define STGB 40960u
#define GSM_BYTES (2 * 40960)    // 81920

__global__ __launch_bounds__(256, 2) void gemm_tc(
    const __nv_bfloat16* __restrict__ Ah, const __nv_bfloat16* __restrict__ Al,
    const __nv_bfloat16* __restrict__ Bh, const __nv_bfloat16* __restrict__ Bl,
    const float* __restrict__ bias, const float* __restrict__ bias2, int nsplit,
    const float* __restrict__ res,
    float* __restrict__ Cf, __nv_bfloat16* __restrict__ Ch,
    __nv_bfloat16* __restrict__ Cl, int M, int N, int K, int relu, float oscale)
{
    extern __shared__ unsigned char smem[];
    const uint32_t sbase = smem_u32(smem);
    const int tid = threadIdx.x;
    const int lane = tid & 31, wid = tid >> 5;
    const int wm = wid >> 2, wn = wid & 3;
    const int row0 = blockIdx.y * 128, col0 = blockIdx.x * 128;

    const __nv_bfloat16* gAh = Ah + (size_t)row0 * K;
    const __nv_bfloat16* gAl = Al + (size_t)row0 * K;
    const __nv_bfloat16* gBh = Bh + (size_t)col0 * K;
    const __nv_bfloat16* gBl = Bl + (size_t)col0 * K;
    const int nch = K >> 5;

    float acc[4][4][4];
    #pragma unroll
    for (int a = 0; a < 4; a++)
        #pragma unroll
        for (int b = 0; b < 4; b++)
            #pragma unroll
            for (int c = 0; c < 4; c++) acc[a][b][c] = 0.f;

    const uint32_t a_base = (uint32_t)(wm * 64 + (lane & 15)) * ROWB +
                            (((lane >> 4) << 3) << 1);
    const uint32_t b_base = (uint32_t)(wn * 32 + ((lane >> 4) << 3) + (lane & 7)) * ROWB +
                            ((((lane >> 3) & 1) << 3) << 1);

    auto load_chunk = [&](int ch, int s) {
        const int k0 = ch << 5;
        const uint32_t st = sbase + s * STGB;
        #pragma unroll
        for (int i = 0; i < 8; i++) {
            const __nv_bfloat16* src = (i < 2) ? gAh : (i < 4) ? gAl
                                     : (i < 6) ? gBh : gBl;
            const int rem = ((i & 1) << 8) + tid;
            const int r = rem >> 2, g = rem & 3;
            cpa16(st + (uint32_t)(i >> 1) * MATB + (uint32_t)r * ROWB + g * 16u,
                  src + (size_t)r * K + k0 + g * 8);
        }
    };

    auto compute_chunk = [&](int s) {
        const uint32_t st = sbase + s * STGB;
        #pragma unroll
        for (int ks = 0; ks < 32; ks += 16) {
            uint32_t aH[4][4], aL[4][4], bH[2][4], bL[2][4];
            const uint32_t ao = a_base + (ks << 1);
            #pragma unroll
            for (int mi = 0; mi < 4; mi++) {
                ldsm4(aH[mi], st + ao + (uint32_t)mi * 16 * ROWB);
                ldsm4(aL[mi], st + MATB + ao + (uint32_t)mi * 16 * ROWB);
            }
            const uint32_t bo = b_base + (ks << 1);
            #pragma unroll
            for (int p = 0; p < 2; p++) {
                ldsm4(bH[p], st + 2 * MATB + bo + (uint32_t)p * 16 * ROWB);
                ldsm4(bL[p], st + 3 * MATB + bo + (uint32_t)p * 16 * ROWB);
            }
            #pragma unroll
            for (int mi = 0; mi < 4; mi++)
                #pragma unroll
                for (int p = 0; p < 2; p++)
                    #pragma unroll
                    for (int h = 0; h < 2; h++) {
                        float* c = acc[mi][p * 2 + h];
                        mma16816(c, aH[mi], &bH[p][h * 2]);
                        mma16816(c, aH[mi], &bL[p][h * 2]);
                        mma16816(c, aL[mi], &bH[p][h * 2]);
                    }
        }
    };

    load_chunk(0, 0); CP_COMMIT();
    load_chunk(1, 1); CP_COMMIT();

    for (int ch = 0; ch < nch; ch++) {
        asm volatile("cp.async.wait_group 1;" ::: "memory");
        __syncthreads();
        compute_chunk(ch & 1);
        __syncthreads();
        if (ch + 2 < nch) load_chunk(ch + 2, ch & 1);
        CP_COMMIT();
    }
    asm volatile("cp.async.wait_group 0;" ::: "memory");

    // ---------------- epilogue ----------------
    // whole 128-col tile is on one side of nsplit (both multiples of 128)
    const float* effb = (bias2 && col0 >= nsplit) ? (bias2 - nsplit) : bias;
    const int tr = lane >> 2, tc = (lane & 3) << 1;
    #pragma unroll
    for (int mi = 0; mi < 4; mi++) {
        #pragma unroll
        for (int ni = 0; ni < 4; ni++) {
            const int col = col0 + wn * 32 + ni * 8 + tc;
            const float2 bb = *(const float2*)&effb[col];
            #pragma unroll
            for (int hr = 0; hr < 2; hr++) {
                const int row = row0 + wm * 64 + mi * 16 + tr + hr * 8;
                float v0 = acc[mi][ni][hr * 2 + 0] + bb.x;
                float v1 = acc[mi][ni][hr * 2 + 1] + bb.y;
                if (relu) { v0 = fmaxf(v0, 0.f); v1 = fmaxf(v1, 0.f); }
                v0 *= oscale; v1 *= oscale;
                const size_t goff = (size_t)row * N + col;
                if (Cf) {
                    if (res) {
                        const float2 rv = *(const float2*)&res[goff];
                        v0 += rv.x; v1 += rv.y;
                    }
                    *(float2*)&Cf[goff] = make_float2(v0, v1);
                } else {
                    uint32_t hp, lp;
                    split2(v0, v1, hp, lp);
                    *(uint32_t*)&Ch[goff] = hp;
                    *(uint32_t*)&Cl[goff] = lp;
                }
            }
        }
    }
}

// ---------------------------------------------------------------------------
// Tensor-core flash attention (causal), bf16x3 precision.
// BM=128, BN=64, 256 threads (8 warps, warp tile 16x64). Q pre-scaled 1/8.
// Q: hi/lo [M][EE], head h at cols h*64. K/V fused: [M][2048], K at h*64,
// V at 1024 + h*64. Out = inp + softmax(QK^T)V (fp32).
// ---------------------------------------------------------------------------
#define AR 144u                   // bytes per smem row (64 bf16 + 8 pad)
#define AQMAT 18432u              // 128 rows * 144B
#define AKMAT 9216u               // 64 rows * 144B
#define ASTG (4 * AKMAT)          // Kh,Kl,Vh,Vl per stage = 36864
#define ATTN_SMEM (2 * AQMAT + 2 * ASTG)   // 110592

__global__ __launch_bounds__(256) void attn_mma(
    const __nv_bfloat16* __restrict__ Qh, const __nv_bfloat16* __restrict__ Ql,
    const __nv_bfloat16* __restrict__ KVh, const __nv_bfloat16* __restrict__ KVl,
    const float* __restrict__ inp, float* __restrict__ Out)
{
    extern __shared__ unsigned char smem[];
    const uint32_t sbase = smem_u32(smem);
    const int tid = threadIdx.x, lane = tid & 31, w = tid >> 5;
    const int qt = blockIdx.x, h = blockIdx.y, b = blockIdx.z;
    const int q0 = qt * 128;
    const int nt = 2 * qt + 2;                 // kv tiles (64 rows each)

    // ---- load Q tile (128 rows, hi+lo) ----
    {
        const size_t ro = (size_t)(b * CC + q0) * EE + (size_t)h * 64;
        #pragma unroll
        for (int i = 0; i < 4; i++) {
            const int idx = i * 256 + tid;
            const int r = idx >> 3, g = idx & 7;
            const uint32_t d = sbase + (uint32_t)r * AR + g * 16u;
            const size_t so = ro + (size_t)r * EE + g * 8;
            cpa16(d, Qh + so);
            cpa16(d + AQMAT, Ql + so);
        }
    }
    CP_COMMIT();

    const size_t kvbase = (size_t)(b * CC) * KVS + (size_t)h * 64;
    auto load_kv = [&](int t, int s) {
        const uint32_t st = sbase + 2 * AQMAT + (uint32_t)s * ASTG;
        const size_t ro = kvbase + (size_t)(t * 64) * KVS;
        #pragma unroll
        for (int i = 0; i < 2; i++) {
            const int idx = i * 256 + tid;
            const int r = idx >> 3, g = idx & 7;
            const uint32_t d = st + (uint32_t)r * AR + g * 16u;
            const size_t so = ro + (size_t)r * KVS + g * 8;
            cpa16(d, KVh + so);
            cpa16(d + AKMAT, KVl + so);
            cpa16(d + 2 * AKMAT, KVh + so + 1024);
            cpa16(d + 3 * AKMAT, KVl + so + 1024);
        }
    };
    load_kv(0, 0); CP_COMMIT();

    float O[8][4];
    #pragma unroll
    for (int n = 0; n < 8; n++)
        #pragma unroll
        for (int j = 0; j < 4; j++) O[n][j] = 0.f;
    float m_lo = -1e30f, m_hi = -1e30f, l_lo = 0.f, l_hi = 0.f;
    uint32_t qHf[4][4], qLf[4][4];

    const int rowl = w * 16 + (lane >> 2);     // local q row (lo); hi = +8
    const int c0 = (lane & 3) << 1;

    for (int t = 0; t < nt; t++) {
        if (t + 1 < nt) load_kv(t + 1, (t + 1) & 1);
        CP_COMMIT();
        asm volatile("cp.async.wait_group 1;" ::: "memory");
        __syncthreads();

        const uint32_t sK = sbase + 2 * AQMAT + (uint32_t)(t & 1) * ASTG;
        const uint32_t sV = sK + 2 * AKMAT;

        if (t == 0) {
            const uint32_t qa = sbase + (uint32_t)(w * 16 + (lane & 15)) * AR +
                                (((lane >> 4) << 3) << 1);
            #pragma unroll
            for (int ks = 0; ks < 4; ks++) {
                ldsm4(qHf[ks], qa + ks * 32);
                ldsm4(qLf[ks], qa + AQMAT + ks * 32);
            }
        }

        // ---- S = Q @ K^T (3-pass) ----
        float S[8][4];
        #pragma unroll
        for (int n = 0; n < 8; n++)
            #pragma unroll
            for (int j = 0; j < 4; j++) S[n][j] = 0.f;

        #pragma unroll
        for (int ks = 0; ks < 4; ks++) {
            #pragma unroll
            for (int np = 0; np < 4; np++) {
                const uint32_t kb = sK +
                    (uint32_t)(np * 16 + ((lane >> 4) << 3) + (lane & 7)) * AR +
                    ((((lane >> 3) & 1) << 3) << 1) + ks * 32;
                uint32_t bh4[4], bl4[4];
                ldsm4(bh4, kb);
                ldsm4(bl4, kb + AKMAT);
                #pragma unroll
                for (int h2 = 0; h2 < 2; h2++) {
                    float* c = S[np * 2 + h2];
                    mma16816(c, qHf[ks], &bh4[h2 * 2]);
                    mma16816(c, qHf[ks], &bl4[h2 * 2]);
                    mma16816(c, qLf[ks], &bh4[h2 * 2]);
                }
            }
        }

        // ---- causal mask (only tiles overlapping/above the diagonal) ----
        if (t >= 2 * qt) {
            const int colg0 = t * 64;
            const int rg_lo = q0 + rowl, rg_hi = rg_lo + 8;
            #pragma unroll
            for (int n = 0; n < 8; n++) {
                const int col = colg0 + n * 8 + c0;
                if (col > rg_lo)     S[n][0] = -1e30f;
                if (col + 1 > rg_lo) S[n][1] = -1e30f;
                if (col > rg_hi)     S[n][2] = -1e30f;
                if (col + 1 > rg_hi) S[n][3] = -1e30f;
            }
        }

        // ---- online softmax ----
        float mx0 = -1e30f, mx1 = -1e30f;
        #pragma unroll
        for (int n = 0; n < 8; n++) {
            mx0 = fmaxf(mx0, fmaxf(S[n][0], S[n][1]));
            mx1 = fmaxf(mx1, fmaxf(S[n][2], S[n][3]));
        }
        mx0 = fmaxf(mx0, __shfl_xor_sync(0xffffffffu, mx0, 1));
        mx0 = fmaxf(mx0, __shfl_xor_sync(0xffffffffu, mx0, 2));
        mx1 = fmaxf(mx1, __shfl_xor_sync(0xffffffffu, mx1, 1));
        mx1 = fmaxf(mx1, __shfl_xor_sync(0xffffffffu, mx1, 2));
        const float mn0 = fmaxf(m_lo, mx0), mn1 = fmaxf(m_hi, mx1);
        const float cr0 = __expf(m_lo - mn0), cr1 = __expf(m_hi - mn1);
        float s0 = 0.f, s1 = 0.f;
        #pragma unroll
        for (int n = 0; n < 8; n++) {
            S[n][0] = __expf(S[n][0] - mn0); s0 += S[n][0];
            S[n][1] = __expf(S[n][1] - mn0); s0 += S[n][1];
            S[n][2] = __expf(S[n][2] - mn1); s1 += S[n][2];
            S[n][3] = __expf(S[n][3] - mn1); s1 += S[n][3];
        }
        s0 += __shfl_xor_sync(0xffffffffu, s0, 1);
        s0 += __shfl_xor_sync(0xffffffffu, s0, 2);
        s1 += __shfl_xor_sync(0xffffffffu, s1, 1);
        s1 += __shfl_xor_sync(0xffffffffu, s1, 2);
        l_lo = l_lo * cr0 + s0; l_hi = l_hi * cr1 + s1;
        m_lo = mn0; m_hi = mn1;
        #pragma unroll
        for (int n = 0; n < 8; n++) {
            O[n][0] *= cr0; O[n][1] *= cr0;
            O[n][2] *= cr1; O[n][3] *= cr1;
        }

        // ---- P -> bf16 hi/lo A-fragments (C-frag reuse) ----
        uint32_t pH[4][4], pL[4][4];
        #pragma unroll
        for (int kk = 0; kk < 4; kk++) {
            split2(S[2 * kk][0],     S[2 * kk][1],     pH[kk][0], pL[kk][0]);
            split2(S[2 * kk][2],     S[2 * kk][3],     pH[kk][1], pL[kk][1]);
            split2(S[2 * kk + 1][0], S[2 * kk + 1][1], pH[kk][2], pL[kk][2]);
            split2(S[2 * kk + 1][2], S[2 * kk + 1][3], pH[kk][3], pL[kk][3]);
        }

        // ---- O += P @ V (3-pass, ldmatrix.trans for V) ----
        #pragma unroll
        for (int kk = 0; kk < 4; kk++) {
            #pragma unroll
            for (int np = 0; np < 4; np++) {
                const uint32_t va = sV +
                    (uint32_t)(kk * 16 + ((lane >> 3) & 1) * 8 + (lane & 7)) * AR +
                    ((np * 16 + ((lane >> 4) << 3)) << 1);
                uint32_t vh4[4], vl4[4];
                ldsm4t(vh4, va);
                ldsm4t(vl4, va + AKMAT);
                #pragma unroll
                for (int h2 = 0; h2 < 2; h2++) {
                    float* c = O[np * 2 + h2];
                    mma16816(c, pH[kk], &vh4[h2 * 2]);
                    mma16816(c, pH[kk], &vl4[h2 * 2]);
                    mma16816(c, pL[kk], &vh4[h2 * 2]);
                }
            }
        }
        __syncthreads();
    }

    // ---- finalize: /l, add residual, store fp32 ----
    const float inv0 = 1.0f / l_lo, inv1 = 1.0f / l_hi;
    const int gr0 = b * CC + q0 + rowl;
    #pragma unroll
    for (int n = 0; n < 8; n++) {
        const int col = h * 64 + n * 8 + c0;
        const size_t o0 = (size_t)gr0 * EE + col;
        const size_t o1 = o0 + (size_t)8 * EE;
        const float2 i0 = *(const float2*)&inp[o0];
        const float2 i1 = *(const float2*)&inp[o1];
        *(float2*)&Out[o0] = make_float2(i0.x + O[n][0] * inv0,
                                         i0.y + O[n][1] * inv0);
        *(float2*)&Out[o1] = make_float2(i1.x + O[n][2] * inv1,
                                         i1.y + O[n][3] * inv1);
    }
}

// ---------------------------------------------------------------------------
// kernel_launch
// ---------------------------------------------------------------------------
extern "C" void kernel_launch(void* const* d_in, const int* in_sizes, int n_in,
                              void* d_out, int out_size)
{
    const float* inputs = (const float*)d_in[0];
    const float* Wq     = (const float*)d_in[1];
    const float* bq     = (const float*)d_in[2];
    const float* Wk     = (const float*)d_in[3];
    const float* bk     = (const float*)d_in[4];
    const float* Wv     = (const float*)d_in[5];
    const float* bv     = (const float*)d_in[6];
    const float* g1     = (const float*)d_in[7];
    const float* beta1  = (const float*)d_in[8];
    const float* g2     = (const float*)d_in[9];
    const float* beta2  = (const float*)d_in[10];
    const float* W1     = (const float*)d_in[11];
    const float* bm1    = (const float*)d_in[12];
    const float* W2     = (const float*)d_in[13];
    const float* bm2    = (const float*)d_in[14];
    float* out = (float*)d_out;

    unsigned char* base = nullptr;
    cudaGetSymbolAddress((void**)&base, g_scratch);
    __nv_bfloat16* nh    = (__nv_bfloat16*)(base + OFF_NH);
    __nv_bfloat16* nl    = (__nv_bfloat16*)(base + OFF_NL);
    __nv_bfloat16* hh    = (__nv_bfloat16*)(base + OFF_HH);
    __nv_bfloat16* hl    = (__nv_bfloat16*)(base + OFF_HL);
    __nv_bfloat16* qh    = (__nv_bfloat16*)(base + OFF_QH);
    __nv_bfloat16* ql    = (__nv_bfloat16*)(base + OFF_QL);
    __nv_bfloat16* kvh   = (__nv_bfloat16*)(base + OFF_KVH);
    __nv_bfloat16* kvl   = (__nv_bfloat16*)(base + OFF_KVL);
    float* outbuf        = (float*)(base + OFF_OUTB);
    __nv_bfloat16* m1h   = (__nv_bfloat16*)(base + OFF_M1H);
    __nv_bfloat16* m1l   = (__nv_bfloat16*)(base + OFF_M1L);
    __nv_bfloat16* WqTh  = (__nv_bfloat16*)(base + OFF_WQH);
    __nv_bfloat16* WqTl  = (__nv_bfloat16*)(base + OFF_WQL);
    __nv_bfloat16* WkvTh = (__nv_bfloat16*)(base + OFF_WKVH);
    __nv_bfloat16* WkvTl = (__nv_bfloat16*)(base + OFF_WKVL);
    __nv_bfloat16* W1Th  = (__nv_bfloat16*)(base + OFF_W1H);
    __nv_bfloat16* W1Tl  = (__nv_bfloat16*)(base + OFF_W1L);
    __nv_bfloat16* W2Th  = (__nv_bfloat16*)(base + OFF_W2H);
    __nv_bfloat16* W2Tl  = (__nv_bfloat16*)(base + OFF_W2L);

    cudaFuncSetAttribute(gemm_tc, cudaFuncAttributeMaxDynamicSharedMemorySize,
                         GSM_BYTES);
    cudaFuncSetAttribute(attn_mma, cudaFuncAttributeMaxDynamicSharedMemorySize,
                         ATTN_SMEM);

    // Launch order chosen so index 3 == gemm_tc (Q proj) for ncu capture.
    // 0: Wq prep
    tsplit_kernel<<<dim3(EE / 32, EE / 32), 256>>>(Wq, WqTh, WqTl, EE, EE);
    // 1: LN1 -> bf16 pair
    ln_kernel<<<MM, 256>>>(inputs, g1, beta1, nh, nl);
    // 2: Wk prep (rows 0..1023 of fused)
    tsplit_kernel<<<dim3(EE / 32, EE / 32), 256>>>(Wk, WkvTh, WkvTl, EE, EE);
    // 3: Q projection (profiled)
    gemm_tc<<<dim3(EE / 128, MM / 128), 256, GSM_BYTES>>>(
        nh, nl, WqTh, WqTl, bq, nullptr, 0, nullptr, nullptr,
        qh, ql, MM, EE, EE, 0, 0.125f);
    // 4: Wv prep (rows 1024..2047 of fused)
    tsplit_kernel<<<dim3(EE / 32, EE / 32), 256>>>(
        Wv, WkvTh + (size_t)1024 * EE, WkvTl + (size_t)1024 * EE, EE, EE);
    // 5: fused K|V projection (N=2048)
    gemm_tc<<<dim3(KVS / 128, MM / 128), 256, GSM_BYTES>>>(
        nh, nl, WkvTh, WkvTl, bk, bv, 1024, nullptr, nullptr,
        kvh, kvl, MM, KVS, EE, 0, 1.0f);
    // 6-7: MLP weight prep
    tsplit_kernel<<<dim3(FF / 32, EE / 32), 256>>>(W1, W1Th, W1Tl, EE, FF);
    tsplit_kernel<<<dim3(EE / 32, FF / 32), 256>>>(W2, W2Th, W2Tl, FF, EE);
    // 8: tensor-core causal attention + residual
    attn_mma<<<dim3(CC / 128, HH, BB), 256, ATTN_SMEM>>>(
        qh, ql, kvh, kvl, inputs, outbuf);
    // 9: LN2 -> bf16 pair
    ln_kernel<<<MM, 256>>>(outbuf, g2, beta2, hh, hl);
    // 10: MLP1 (relu) -> bf16 pair
    gemm_tc<<<dim3(FF / 128, MM / 128), 256, GSM_BYTES>>>(
        hh, hl, W1Th, W1Tl, bm1, nullptr, 0, nullptr, nullptr,
        m1h, m1l, MM, FF, EE, 1, 1.0f);
    // 11: MLP2 + residual -> out
    gemm_tc<<<dim3(EE / 128, MM / 128), 256, GSM_BYTES>>>(
        m1h, m1l, W2Th, W2Tl, bm2, nullptr, 0, outbuf, out,
        nullptr, nullptr, MM, EE, FF, 0, 1.0f);
}